// round 12
// baseline (speedup 1.0000x reference)
#include <cuda_runtime.h>
#include <cuda_fp16.h>
#include <math.h>
#include <stdint.h>

typedef unsigned long long ull;
#define CLAMPV 10000.0f

// ---------------- static scratch ----------------
__device__ float g_xproj[16777216];   // [BL*T,128]
__device__ float g_k15[245760];       // [BL][15][128]
__device__ float g_v15[245760];
__device__ float g_rproj[40960];      // [32*10][128]
__device__ float g_buf[163840];       // [BL][2][10][64]
__device__ __half g_w16[262144];      // m1w1|m1w2|m2w1|m2w2 (fp16)
__device__ __half g_m2[524288];       // [BL][128][32] fp16 (Wq @ buf)
__device__ float g_c2[4096];          // [BL][32]  (bq . buf_j)

// ---------------- helpers ----------------
__device__ __forceinline__ float gelu_fast(float x) {
    float u = 0.7978845608f * x * (1.0f + 0.044715f * x * x);
    float t; asm("tanh.approx.f32 %0, %1;" : "=f"(t) : "f"(u));
    return 0.5f * x * (1.0f + t);
}
__device__ __forceinline__ uint32_t su32(const void* p) {
    uint32_t a;
    asm("{ .reg .u64 t; cvta.to.shared.u64 t, %1; cvt.u32.u64 %0, t; }" : "=r"(a) : "l"(p));
    return a;
}
__device__ __forceinline__ ull pack4h(float4 v) {
    unsigned short a = __half_as_ushort(__float2half_rn(v.x));
    unsigned short b = __half_as_ushort(__float2half_rn(v.y));
    unsigned short c = __half_as_ushort(__float2half_rn(v.z));
    unsigned short d = __half_as_ushort(__float2half_rn(v.w));
    return (ull)a | ((ull)b << 16) | ((ull)c << 32) | ((ull)d << 48);
}

// ---------------- tensor-core primitives ----------------
__device__ __forceinline__ void ldmx4(uint32_t* r, uint32_t addr) {
    asm volatile("ldmatrix.sync.aligned.m8n8.x4.shared.b16 {%0,%1,%2,%3}, [%4];"
        : "=r"(r[0]), "=r"(r[1]), "=r"(r[2]), "=r"(r[3]) : "r"(addr));
}
__device__ __forceinline__ void ldmx4t(uint32_t* r, uint32_t addr) {
    asm volatile("ldmatrix.sync.aligned.m8n8.x4.trans.shared.b16 {%0,%1,%2,%3}, [%4];"
        : "=r"(r[0]), "=r"(r[1]), "=r"(r[2]), "=r"(r[3]) : "r"(addr));
}
__device__ __forceinline__ void mma16816(float* c, const uint32_t* a, const uint32_t* b) {
    asm volatile("mma.sync.aligned.m16n8k16.row.col.f32.f16.f16.f32 "
        "{%0,%1,%2,%3}, {%4,%5,%6,%7}, {%8,%9}, {%0,%1,%2,%3};"
        : "+f"(c[0]), "+f"(c[1]), "+f"(c[2]), "+f"(c[3])
        : "r"(a[0]), "r"(a[1]), "r"(a[2]), "r"(a[3]), "r"(b[0]), "r"(b[1]));
}

// ============ weight pre-conversion ============
__global__ void cvt_weights(const float* __restrict__ w1a, const float* __restrict__ w2a,
                            const float* __restrict__ w1b, const float* __restrict__ w2b,
                            __half* __restrict__ o)
{
    int i = blockIdx.x * 256 + threadIdx.x;
    if (i >= 262144) return;
    float v;
    if (i < 65536) v = w1a[i];
    else if (i < 131072) v = w2a[i - 65536];
    else if (i < 196608) v = w1b[i - 131072];
    else v = w2b[i - 196608];
    o[i] = __float2half_rn(v);
}

// ---------------- shared smem layout (64-row tiles, occ=2, dual W buffers) ----------------
#define RPITCH 272
#define SM_X   0        // 64*272 = 17408
#define SM_W1  17408    // 128*272 = 34816
#define SM_W2  52224    // 128*272 = 34816
#define SM_H   87040    // 64*272 = 17408
#define SM_P   104448   // 4*64 float2 = 2048
#define SMEM_A 106496
#define SM_BUF 106496   // 1280 floats (kernel B)
#define SM_C2  111616   // 32 floats
#define SMEM_B 111744

// ======================================================================
// Kernel A: gather x -> MLP1 (fp16 mma) -> +x -> LN(g1) -> xproj
// 64 rows/CTA, 256 threads, 8 warps (2x4 grid of 32x32 tiles), occ=2
// ======================================================================
__global__ __launch_bounds__(256, 2) void fused_mlp1(
    const float* __restrict__ in,
    const __half* __restrict__ w1h, const float* __restrict__ b1,
    const __half* __restrict__ w2h, const float* __restrict__ b2,
    const float* __restrict__ ga, const float* __restrict__ ba,
    float* __restrict__ xproj)
{
    extern __shared__ char smem[];
    const int tid = threadIdx.x;
    const int wid = tid >> 5;
    const int lane = tid & 31;
    const int R0 = blockIdx.x * 64;
    const int bl0 = R0 >> 10;
    const int bI = bl0 >> 5, lI = bl0 & 31, tb0 = R0 & 1023;
    const uint32_t sb = su32(smem);
    float2* part = (float2*)(smem + SM_P);

    // ---- stage X fp16 (gathered) ----
#pragma unroll
    for (int i = 0; i < 8; i++) {
        int idx = tid + i * 256;
        int m = idx >> 5, k4 = (idx & 31) * 4;
        int grow = (((bI << 10) + tb0 + m) << 5) + lI;
        float4 v = *(const float4*)(in + grow * 128 + k4);
        *(ull*)(smem + SM_X + m * RPITCH + k4 * 2) = pack4h(v);
    }

    const int wm = (wid >> 2) * 32;
    const int wn = (wid & 3) * 32;
    const int l4 = lane >> 2, lc = (lane & 3) * 2;
    const uint32_t aoffs = (uint32_t)((((lane >> 3) & 1) * 8 + (lane & 7)) * RPITCH
                                      + (((lane >> 4) & 1) * 8) * 2);

    float o[2][4][4];
#pragma unroll
    for (int ni = 0; ni < 4; ni++) {
        int col = wn + ni * 8 + lc;
        float bv0 = __ldg(&b2[col]), bv1 = __ldg(&b2[col + 1]);
#pragma unroll
        for (int mi = 0; mi < 2; mi++) {
            o[mi][ni][0] = bv0; o[mi][ni][1] = bv1;
            o[mi][ni][2] = bv0; o[mi][ni][3] = bv1;
        }
    }

    for (int ch = 0; ch < 4; ch++) {
        __syncthreads();                 // prior GEMM2 done with W2/H; X ready
        // stage W1[ch] and W2[ch] together
#pragma unroll
        for (int i = 0; i < 8; i++) {
            int idx = tid + i * 256;
            int k = idx >> 4, j = idx & 15;
            *(int4*)(smem + SM_W1 + k * RPITCH + j * 16) =
                *(const int4*)(w1h + k * 512 + ch * 128 + j * 8);
            *(int4*)(smem + SM_W2 + k * RPITCH + j * 16) =
                *(const int4*)(w2h + (ch * 128 + k) * 128 + j * 8);
        }
        __syncthreads();

        float h[2][4][4];
#pragma unroll
        for (int ni = 0; ni < 4; ni++) {
            int col = wn + ni * 8 + lc;
            float bv0 = __ldg(&b1[ch * 128 + col]), bv1 = __ldg(&b1[ch * 128 + col + 1]);
#pragma unroll
            for (int mi = 0; mi < 2; mi++) {
                h[mi][ni][0] = bv0; h[mi][ni][1] = bv1;
                h[mi][ni][2] = bv0; h[mi][ni][3] = bv1;
            }
        }
#pragma unroll 2
        for (int ks = 0; ks < 8; ks++) {
            int k0 = ks * 16;
            uint32_t a[2][4], b[8];
#pragma unroll
            for (int mi = 0; mi < 2; mi++)
                ldmx4(a[mi], sb + SM_X + (wm + mi * 16) * RPITCH + k0 * 2 + aoffs);
            ldmx4t(b,     sb + SM_W1 + k0 * RPITCH + wn * 2 + aoffs);
            ldmx4t(b + 4, sb + SM_W1 + k0 * RPITCH + (wn + 16) * 2 + aoffs);
#pragma unroll
            for (int mi = 0; mi < 2; mi++)
#pragma unroll
                for (int ni = 0; ni < 4; ni++)
                    mma16816(h[mi][ni], a[mi], b + 2 * ni);
        }
#pragma unroll
        for (int mi = 0; mi < 2; mi++)
#pragma unroll
            for (int ni = 0; ni < 4; ni++) {
                int r_ = wm + mi * 16 + l4;
                int cb = (wn + ni * 8 + lc) * 2;
                unsigned short h0 = __half_as_ushort(__float2half_rn(gelu_fast(h[mi][ni][0])));
                unsigned short h1 = __half_as_ushort(__float2half_rn(gelu_fast(h[mi][ni][1])));
                unsigned short h2 = __half_as_ushort(__float2half_rn(gelu_fast(h[mi][ni][2])));
                unsigned short h3 = __half_as_ushort(__float2half_rn(gelu_fast(h[mi][ni][3])));
                *(uint32_t*)(smem + SM_H + r_ * RPITCH + cb) = (uint32_t)h0 | ((uint32_t)h1 << 16);
                *(uint32_t*)(smem + SM_H + (r_ + 8) * RPITCH + cb) = (uint32_t)h2 | ((uint32_t)h3 << 16);
            }
        __syncthreads();                 // H visible
#pragma unroll 2
        for (int ks = 0; ks < 8; ks++) {
            int k0 = ks * 16;
            uint32_t a[2][4], b[8];
#pragma unroll
            for (int mi = 0; mi < 2; mi++)
                ldmx4(a[mi], sb + SM_H + (wm + mi * 16) * RPITCH + k0 * 2 + aoffs);
            ldmx4t(b,     sb + SM_W2 + k0 * RPITCH + wn * 2 + aoffs);
            ldmx4t(b + 4, sb + SM_W2 + k0 * RPITCH + (wn + 16) * 2 + aoffs);
#pragma unroll
            for (int mi = 0; mi < 2; mi++)
#pragma unroll
                for (int ni = 0; ni < 4; ni++)
                    mma16816(o[mi][ni], a[mi], b + 2 * ni);
        }
    }

    // ---- epilogue: dump -> +x -> LN -> xproj ----
    __syncthreads();
    float* OB = (float*)(smem);                // [64][132] overlays X/W1
#pragma unroll
    for (int mi = 0; mi < 2; mi++)
#pragma unroll
        for (int ni = 0; ni < 4; ni++) {
            int r_ = wm + mi * 16 + l4;
            int c_ = wn + ni * 8 + lc;
            *(float2*)(OB + r_ * 132 + c_) = make_float2(o[mi][ni][0], o[mi][ni][1]);
            *(float2*)(OB + (r_ + 8) * 132 + c_) = make_float2(o[mi][ni][2], o[mi][ni][3]);
        }
    __syncthreads();

    const int m = tid & 63, cq = tid >> 6;
    const int c0 = cq * 32;
    float v[32];
    {
        int grow = (((bI << 10) + tb0 + m) << 5) + lI;
        const float* rp = in + grow * 128 + c0;
#pragma unroll
        for (int g = 0; g < 8; g++) {
            float4 u = *(const float4*)(rp + 4 * g);
            float4 a = *(const float4*)(OB + m * 132 + c0 + 4 * g);
            v[4 * g + 0] = a.x + u.x; v[4 * g + 1] = a.y + u.y;
            v[4 * g + 2] = a.z + u.z; v[4 * g + 3] = a.w + u.w;
        }
    }
    {
        float s = 0.f, q = 0.f;
#pragma unroll
        for (int j = 0; j < 32; j++) { s += v[j]; q += v[j] * v[j]; }
        part[cq * 64 + m] = make_float2(s, q);
    }
    __syncthreads();
    {
        float s = 0.f, q = 0.f;
#pragma unroll
        for (int p_ = 0; p_ < 4; p_++) {
            float2 pp = part[p_ * 64 + m];
            s += pp.x; q += pp.y;
        }
        float mean = s * 0.0078125f;
        float rstd = rsqrtf(fmaxf(q * 0.0078125f - mean * mean, 0.f) + 1e-5f);
#pragma unroll
        for (int j = 0; j < 32; j++)
            v[j] = (v[j] - mean) * rstd * __ldg(&ga[c0 + j]) + __ldg(&ba[c0 + j]);
    }
    const int Rg = R0 + m;
#pragma unroll
    for (int g = 0; g < 8; g++)
        *(float4*)(xproj + Rg * 128 + c0 + 4 * g) =
            make_float4(v[4 * g], v[4 * g + 1], v[4 * g + 2], v[4 * g + 3]);
}

// ======================================================================
// Kernel B: scores via M2 (mma) -> softmax/recv -> MLP2 -> +xproj
//           -> LN(g2) -> LN(g3) -> scatter. 64 rows/CTA, occ=2.
// ======================================================================
__global__ __launch_bounds__(256, 2) void fused_recv_mlp2(
    const float* __restrict__ bufp, const float* __restrict__ xproj,
    const __half* __restrict__ m2, const float* __restrict__ c2,
    const __half* __restrict__ w1h, const float* __restrict__ b1,
    const __half* __restrict__ w2h, const float* __restrict__ b2,
    const float* __restrict__ ga, const float* __restrict__ ba,
    const float* __restrict__ gb, const float* __restrict__ bb,
    float* __restrict__ out)
{
    extern __shared__ char smem[];
    const int tid = threadIdx.x;
    const int wid = tid >> 5;
    const int lane = tid & 31;
    const int R0 = blockIdx.x * 64;
    const int bl0 = R0 >> 10;
    const int bI = bl0 >> 5, lI = bl0 & 31, tb0 = R0 & 1023;
    const uint32_t sb = su32(smem);
    float2* part = (float2*)(smem + SM_P);
    float* BUFS = (float*)(smem + SM_BUF);
    float* C2S  = (float*)(smem + SM_C2);
    float* SC   = (float*)(smem + SM_H);     // scores [64][36]

    // ---- stage BUFS, M2 tile (SM_W1), c2, xproj fp16 (SM_X) ----
    for (int idx = tid; idx < 1280; idx += 256)
        BUFS[idx] = bufp[bl0 * 1280 + idx];
#pragma unroll
    for (int i = 0; i < 2; i++) {
        int idx = tid + i * 256;
        int k = idx >> 2, seg = idx & 3;
        *(int4*)(smem + SM_W1 + k * RPITCH + seg * 16) =
            *(const int4*)(m2 + (bl0 << 12) + (k << 5) + seg * 8);
    }
    if (tid < 32) C2S[tid] = c2[(bl0 << 5) + tid];
#pragma unroll
    for (int i = 0; i < 8; i++) {
        int idx = tid + i * 256;
        int m_ = idx >> 5, k4 = (idx & 31) * 4;
        float4 v = *(const float4*)(xproj + (R0 + m_) * 128 + k4);
        *(ull*)(smem + SM_X + m_ * RPITCH + k4 * 2) = pack4h(v);
    }
    __syncthreads();

    const int l4 = lane >> 2, lc = (lane & 3) * 2;
    const uint32_t aoffs = (uint32_t)((((lane >> 3) & 1) * 8 + (lane & 7)) * RPITCH
                                      + (((lane >> 4) & 1) * 8) * 2);

    // ---- score mma: rows 0..63 x [k=128] x [n=32]; warps 0..3 ----
    if (wid < 4) {
        const int wm2 = wid * 16;
        float sc[4][4];
#pragma unroll
        for (int ni = 0; ni < 4; ni++) { sc[ni][0] = sc[ni][1] = sc[ni][2] = sc[ni][3] = 0.f; }
#pragma unroll 2
        for (int ks = 0; ks < 8; ks++) {
            int k0 = ks * 16;
            uint32_t a[4], b[8];
            ldmx4(a, sb + SM_X + wm2 * RPITCH + k0 * 2 + aoffs);
            ldmx4t(b,     sb + SM_W1 + k0 * RPITCH + aoffs);
            ldmx4t(b + 4, sb + SM_W1 + k0 * RPITCH + 32 + aoffs);
#pragma unroll
            for (int ni = 0; ni < 4; ni++)
                mma16816(sc[ni], a, b + 2 * ni);
        }
#pragma unroll
        for (int ni = 0; ni < 4; ni++) {
            int n = ni * 8 + lc;
            *(float2*)(SC + (wm2 + l4) * 36 + n)     = make_float2(sc[ni][0], sc[ni][1]);
            *(float2*)(SC + (wm2 + l4 + 8) * 36 + n) = make_float2(sc[ni][2], sc[ni][3]);
        }
    }
    __syncthreads();

    // ---- softmax + recv: thread = (r 0..63, hd, half32) ----
    {
        const int r = tid & 63, hd = (tid >> 6) & 1, hf = tid >> 7;
        const int t = tb0 + r;
        float s[10];
#pragma unroll
        for (int j = 0; j < 10; j++) {
            float sv = (SC[r * 36 + hd * 16 + j] + C2S[hd * 16 + j]) * 0.125f;
            s[j] = fminf(fmaxf(sv, -CLAMPV), CLAMPV);
        }
        bool all = (t >= 10);
        float mx = -1e30f;
#pragma unroll
        for (int j = 0; j < 10; j++) {
            bool a = all || (j >= t - 5 && j <= t + 5);
            if (a) mx = fmaxf(mx, s[j]);
        }
        float p[10], den = 0.f;
#pragma unroll
        for (int j = 0; j < 10; j++) {
            bool a = all || (j >= t - 5 && j <= t + 5);
            p[j] = a ? expf(s[j] - mx) : 0.f;
            den += p[j];
        }
        float rinv = 1.f / den;
#pragma unroll
        for (int j = 0; j < 10; j++) p[j] *= rinv;
        const float* BF = BUFS + hd * 640 + hf * 32;
#pragma unroll
        for (int g = 0; g < 8; g++) {
            float4 acc = make_float4(0.f, 0.f, 0.f, 0.f);
#pragma unroll
            for (int j = 0; j < 10; j++) {
                float4 bv = *(const float4*)(BF + j * 64 + 4 * g);
                acc.x += p[j] * bv.x; acc.y += p[j] * bv.y;
                acc.z += p[j] * bv.z; acc.w += p[j] * bv.w;
            }
            *(ull*)(smem + SM_X + r * RPITCH + (hd * 64 + hf * 32 + 4 * g) * 2) = pack4h(acc);
        }
    }

    const int wm = (wid >> 2) * 32;
    const int wn = (wid & 3) * 32;

    float o[2][4][4];
#pragma unroll
    for (int ni = 0; ni < 4; ni++) {
        int col = wn + ni * 8 + lc;
        float bv0 = __ldg(&b2[col]), bv1 = __ldg(&b2[col + 1]);
#pragma unroll
        for (int mi = 0; mi < 2; mi++) {
            o[mi][ni][0] = bv0; o[mi][ni][1] = bv1;
            o[mi][ni][2] = bv0; o[mi][ni][3] = bv1;
        }
    }

    for (int ch = 0; ch < 4; ch++) {
        __syncthreads();
#pragma unroll
        for (int i = 0; i < 8; i++) {
            int idx = tid + i * 256;
            int k = idx >> 4, j = idx & 15;
            *(int4*)(smem + SM_W1 + k * RPITCH + j * 16) =
                *(const int4*)(w1h + k * 512 + ch * 128 + j * 8);
            *(int4*)(smem + SM_W2 + k * RPITCH + j * 16) =
                *(const int4*)(w2h + (ch * 128 + k) * 128 + j * 8);
        }
        __syncthreads();

        float h[2][4][4];
#pragma unroll
        for (int ni = 0; ni < 4; ni++) {
            int col = wn + ni * 8 + lc;
            float bv0 = __ldg(&b1[ch * 128 + col]), bv1 = __ldg(&b1[ch * 128 + col + 1]);
#pragma unroll
            for (int mi = 0; mi < 2; mi++) {
                h[mi][ni][0] = bv0; h[mi][ni][1] = bv1;
                h[mi][ni][2] = bv0; h[mi][ni][3] = bv1;
            }
        }
#pragma unroll 2
        for (int ks = 0; ks < 8; ks++) {
            int k0 = ks * 16;
            uint32_t a[2][4], b[8];
#pragma unroll
            for (int mi = 0; mi < 2; mi++)
                ldmx4(a[mi], sb + SM_X + (wm + mi * 16) * RPITCH + k0 * 2 + aoffs);
            ldmx4t(b,     sb + SM_W1 + k0 * RPITCH + wn * 2 + aoffs);
            ldmx4t(b + 4, sb + SM_W1 + k0 * RPITCH + (wn + 16) * 2 + aoffs);
#pragma unroll
            for (int mi = 0; mi < 2; mi++)
#pragma unroll
                for (int ni = 0; ni < 4; ni++)
                    mma16816(h[mi][ni], a[mi], b + 2 * ni);
        }
#pragma unroll
        for (int mi = 0; mi < 2; mi++)
#pragma unroll
            for (int ni = 0; ni < 4; ni++) {
                int r_ = wm + mi * 16 + l4;
                int cb = (wn + ni * 8 + lc) * 2;
                unsigned short h0 = __half_as_ushort(__float2half_rn(gelu_fast(h[mi][ni][0])));
                unsigned short h1 = __half_as_ushort(__float2half_rn(gelu_fast(h[mi][ni][1])));
                unsigned short h2 = __half_as_ushort(__float2half_rn(gelu_fast(h[mi][ni][2])));
                unsigned short h3 = __half_as_ushort(__float2half_rn(gelu_fast(h[mi][ni][3])));
                *(uint32_t*)(smem + SM_H + r_ * RPITCH + cb) = (uint32_t)h0 | ((uint32_t)h1 << 16);
                *(uint32_t*)(smem + SM_H + (r_ + 8) * RPITCH + cb) = (uint32_t)h2 | ((uint32_t)h3 << 16);
            }
        __syncthreads();
#pragma unroll 2
        for (int ks = 0; ks < 8; ks++) {
            int k0 = ks * 16;
            uint32_t a[2][4], b[8];
#pragma unroll
            for (int mi = 0; mi < 2; mi++)
                ldmx4(a[mi], sb + SM_H + (wm + mi * 16) * RPITCH + k0 * 2 + aoffs);
            ldmx4t(b,     sb + SM_W2 + k0 * RPITCH + wn * 2 + aoffs);
            ldmx4t(b + 4, sb + SM_W2 + k0 * RPITCH + (wn + 16) * 2 + aoffs);
#pragma unroll
            for (int mi = 0; mi < 2; mi++)
#pragma unroll
                for (int ni = 0; ni < 4; ni++)
                    mma16816(o[mi][ni], a[mi], b + 2 * ni);
        }
    }

    // ---- epilogue: +xproj, LN(g2), LN(g3), scatter ----
    __syncthreads();
    float* OB = (float*)(smem);
#pragma unroll
    for (int mi = 0; mi < 2; mi++)
#pragma unroll
        for (int ni = 0; ni < 4; ni++) {
            int r_ = wm + mi * 16 + l4;
            int c_ = wn + ni * 8 + lc;
            *(float2*)(OB + r_ * 132 + c_) = make_float2(o[mi][ni][0], o[mi][ni][1]);
            *(float2*)(OB + (r_ + 8) * 132 + c_) = make_float2(o[mi][ni][2], o[mi][ni][3]);
        }
    __syncthreads();

    const int m = tid & 63, cq = tid >> 6;
    const int c0 = cq * 32;
    float v[32];
    {
        const float* rp = xproj + (R0 + m) * 128 + c0;
#pragma unroll
        for (int g = 0; g < 8; g++) {
            float4 u = *(const float4*)(rp + 4 * g);
            float4 a = *(const float4*)(OB + m * 132 + c0 + 4 * g);
            v[4 * g + 0] = a.x + u.x; v[4 * g + 1] = a.y + u.y;
            v[4 * g + 2] = a.z + u.z; v[4 * g + 3] = a.w + u.w;
        }
    }
    {
        float s = 0.f, q = 0.f;
#pragma unroll
        for (int j = 0; j < 32; j++) { s += v[j]; q += v[j] * v[j]; }
        part[cq * 64 + m] = make_float2(s, q);
    }
    __syncthreads();
    {
        float s = 0.f, q = 0.f;
#pragma unroll
        for (int p_ = 0; p_ < 4; p_++) {
            float2 pp = part[p_ * 64 + m];
            s += pp.x; q += pp.y;
        }
        float mean = s * 0.0078125f;
        float rstd = rsqrtf(fmaxf(q * 0.0078125f - mean * mean, 0.f) + 1e-5f);
#pragma unroll
        for (int j = 0; j < 32; j++)
            v[j] = (v[j] - mean) * rstd * __ldg(&ga[c0 + j]) + __ldg(&ba[c0 + j]);
    }
    __syncthreads();
    {
        float s = 0.f, q = 0.f;
#pragma unroll
        for (int j = 0; j < 32; j++) { s += v[j]; q += v[j] * v[j]; }
        part[cq * 64 + m] = make_float2(s, q);
    }
    __syncthreads();
    float s = 0.f, q = 0.f;
#pragma unroll
    for (int p_ = 0; p_ < 4; p_++) {
        float2 pp = part[p_ * 64 + m];
        s += pp.x; q += pp.y;
    }
    float m2v = s * 0.0078125f;
    float rstd2 = rsqrtf(fmaxf(q * 0.0078125f - m2v * m2v, 0.f) + 1e-5f);
    int t = tb0 + m;
    int ob = (((bI << 10) + t) * 32 + lI) * 128 + c0;
#pragma unroll
    for (int g = 0; g < 8; g++) {
        float4 w;
        w.x = (v[4 * g + 0] - m2v) * rstd2 * __ldg(&gb[c0 + 4 * g + 0]) + __ldg(&bb[c0 + 4 * g + 0]);
        w.y = (v[4 * g + 1] - m2v) * rstd2 * __ldg(&gb[c0 + 4 * g + 1]) + __ldg(&bb[c0 + 4 * g + 1]);
        w.z = (v[4 * g + 2] - m2v) * rstd2 * __ldg(&gb[c0 + 4 * g + 2]) + __ldg(&bb[c0 + 4 * g + 2]);
        w.w = (v[4 * g + 3] - m2v) * rstd2 * __ldg(&gb[c0 + 4 * g + 3]) + __ldg(&bb[c0 + 4 * g + 3]);
        *(float4*)(out + ob + 4 * g) = w;
    }
}

// ============ merged K/V projection (blocks 0..127) + router proj (128..137) ============
#define SMEM_KV (34688 * 4)
__global__ __launch_bounds__(256, 1) void kvr_kernel(
    const float* __restrict__ xp,
    const float* __restrict__ wk, const float* __restrict__ bk,
    const float* __restrict__ wv, const float* __restrict__ bv,
    const float* __restrict__ router, const float* __restrict__ wr, const float* __restrict__ br,
    float* __restrict__ k15, float* __restrict__ v15, float* __restrict__ rp)
{
    extern __shared__ float sm[];
    const int tid = threadIdx.x;
    if (blockIdx.x < 128) {
        float* Xs = sm;
        float* Wks = sm + 1920;
        float* Wvs = sm + 18304;
        const int bl = blockIdx.x;
        for (int idx = tid; idx < 1920; idx += 256)
            Xs[idx] = xp[(bl * 1024 + (idx >> 7)) * 128 + (idx & 127)];
        for (int idx = tid; idx < 16384; idx += 256) { Wks[idx] = wk[idx]; Wvs[idx] = wv[idx]; }
        __syncthreads();
        const int m = tid >> 7, n = tid & 127;
        const float* W = m ? Wvs : Wks;
        const float bsv = m ? __ldg(&bv[n]) : __ldg(&bk[n]);
        float* o = m ? v15 : k15;
        for (int t = 0; t < 15; t++) {
            float acc = bsv;
#pragma unroll 8
            for (int k = 0; k < 128; k++) acc += Xs[t * 128 + k] * W[k * 128 + n];
            o[(bl * 15 + t) * 128 + n] = acc;
        }
    } else {
        float* Ws = sm;
        float* Rs = sm + 16384;
        const int row0 = (blockIdx.x - 128) * 32;
        for (int idx = tid; idx < 16384; idx += 256) Ws[idx] = wr[idx];
        for (int idx = tid; idx < 4096; idx += 256)
            Rs[idx] = router[(row0 + (idx >> 7)) * 128 + (idx & 127)];
        __syncthreads();
        const int n = tid & 127, rbase = (tid >> 7) * 16;
        const float bb_ = __ldg(&br[n]);
        for (int rr = 0; rr < 16; rr++) {
            int r = rbase + rr;
            float acc = bb_;
#pragma unroll 8
            for (int k = 0; k < 128; k++) acc += Rs[r * 128 + k] * Ws[k * 128 + n];
            rp[(row0 + r) * 128 + n] = acc;
        }
    }
}

// ============ buffer attention: warp per (bl, h, i) ============
__global__ __launch_bounds__(256) void buffer_warp(
    const float* __restrict__ rp, const float* __restrict__ k15,
    const float* __restrict__ v15, float* __restrict__ buf)
{
    const int w = (blockIdx.x << 3) + (threadIdx.x >> 5);
    const int lane = threadIdx.x & 31;
    const int bl = w / 20;
    const int rem = w - bl * 20;
    const int h = rem / 10, i = rem - (rem / 10) * 10;
    const int l = bl & 31;
    const float* q = rp + (l * 10 + i) * 128 + h * 64;
    const float q0 = q[lane], q1 = q[lane + 32];
    const int jlo = (i > 5) ? (i - 5) : 0;
    const int cnt = i + 5 - jlo + 1;
    float s[11];
#pragma unroll
    for (int jj = 0; jj < 11; jj++) {
        float d = 0.f;
        if (jj < cnt) {
            int base = (bl * 15 + jlo + jj) * 128 + h * 64;
            d = q0 * k15[base + lane] + q1 * k15[base + lane + 32];
        }
        d += __shfl_xor_sync(0xffffffffu, d, 16);
        d += __shfl_xor_sync(0xffffffffu, d, 8);
        d += __shfl_xor_sync(0xffffffffu, d, 4);
        d += __shfl_xor_sync(0xffffffffu, d, 2);
        d += __shfl_xor_sync(0xffffffffu, d, 1);
        s[jj] = fminf(fmaxf(d * 0.125f, -CLAMPV), CLAMPV);
    }
    float mx = -1e30f;
#pragma unroll
    for (int jj = 0; jj < 11; jj++) if (jj < cnt) mx = fmaxf(mx, s[jj]);
    float den = 0.f, o0 = 0.f, o1 = 0.f;
#pragma unroll
    for (int jj = 0; jj < 11; jj++) {
        if (jj < cnt) {
            float p = expf(s[jj] - mx);
            den += p;
            int vbase = (bl * 15 + jlo + jj) * 128 + h * 64;
            o0 += p * v15[vbase + lane];
            o1 += p * v15[vbase + lane + 32];
        }
    }
    float rinv = 1.f / den;
    int ob = ((bl * 2 + h) * 10 + i) * 64;
    buf[ob + lane] = o0 * rinv;
    buf[ob + lane + 32] = o1 * rinv;
}

// ============ M2 = Wq @ buf^T per (bl), fp16; c2 = bq . buf ============
__global__ __launch_bounds__(256) void m2_kernel(
    const float* __restrict__ wq, const float* __restrict__ bq,
    const float* __restrict__ bufp, __half* __restrict__ m2, float* __restrict__ c2)
{
    __shared__ float bufS[1280];
    const int bl = blockIdx.x, tid = threadIdx.x;
    for (int idx = tid; idx < 1280; idx += 256) bufS[idx] = bufp[bl * 1280 + idx];
    __syncthreads();
    const int n = tid & 31, h = n >> 4, j = n & 15;
    const float* bv = bufS + h * 640 + j * 64;
#pragma unroll 1
    for (int it = 0; it < 16; it++) {
        int k = (tid >> 5) + (it << 3);
        float acc = 0.f;
        if (j < 10) {
            const float* wr = wq + k * 128 + h * 64;
#pragma unroll 8
            for (int d = 0; d < 64; d++) acc += wr[d] * bv[d];
        }
        m2[(bl << 12) + (k << 5) + n] = __float2half_rn(acc);
    }
    if (tid < 32) {
        float c = 0.f;
        if (j < 10) {
            const float* br_ = bq + h * 64;
#pragma unroll 8
            for (int d = 0; d < 64; d++) c += br_[d] * bv[d];
        }
        c2[(bl << 5) + tid] = c;
    }
}

// ============ launch ============
extern "C" void kernel_launch(void* const* d_in, const int* in_sizes, int n_in,
                              void* d_out, int out_size)
{
    const float* x        = (const float*)d_in[0];
    const float* router   = (const float*)d_in[1];
    const float* w_router = (const float*)d_in[2];
    const float* b_router = (const float*)d_in[3];
    const float* w_k      = (const float*)d_in[4];
    const float* b_k      = (const float*)d_in[5];
    const float* w_v      = (const float*)d_in[6];
    const float* b_v      = (const float*)d_in[7];
    const float* w_q      = (const float*)d_in[8];
    const float* b_q      = (const float*)d_in[9];
    const float* m1w1 = (const float*)d_in[10];
    const float* m1b1 = (const float*)d_in[11];
    const float* m1w2 = (const float*)d_in[12];
    const float* m1b2 = (const float*)d_in[13];
    const float* m2w1 = (const float*)d_in[14];
    const float* m2b1 = (const float*)d_in[15];
    const float* m2w2 = (const float*)d_in[16];
    const float* m2b2 = (const float*)d_in[17];
    const float* g1  = (const float*)d_in[18];
    const float* be1 = (const float*)d_in[19];
    const float* g2  = (const float*)d_in[20];
    const float* be2 = (const float*)d_in[21];
    const float* g3  = (const float*)d_in[22];
    const float* be3 = (const float*)d_in[23];
    float* out = (float*)d_out;

    float *xproj, *k15, *v15, *rproj, *bufp, *c2p;
    __half *w16, *m2p;
    cudaGetSymbolAddress((void**)&xproj, g_xproj);
    cudaGetSymbolAddress((void**)&k15,   g_k15);
    cudaGetSymbolAddress((void**)&v15,   g_v15);
    cudaGetSymbolAddress((void**)&rproj, g_rproj);
    cudaGetSymbolAddress((void**)&bufp,  g_buf);
    cudaGetSymbolAddress((void**)&w16,   g_w16);
    cudaGetSymbolAddress((void**)&m2p,   g_m2);
    cudaGetSymbolAddress((void**)&c2p,   g_c2);

    cudaFuncSetAttribute(fused_mlp1, cudaFuncAttributeMaxDynamicSharedMemorySize, SMEM_A);
    cudaFuncSetAttribute(fused_recv_mlp2, cudaFuncAttributeMaxDynamicSharedMemorySize, SMEM_B);
    cudaFuncSetAttribute(kvr_kernel, cudaFuncAttributeMaxDynamicSharedMemorySize, SMEM_KV);

    // 0. weights -> fp16
    cvt_weights<<<1024, 256>>>(m1w1, m1w2, m2w1, m2w2, w16);
    // 1. x_proj = LN(x + mlp1(x))   [64 rows/CTA, occ=2]
    fused_mlp1<<<2048, 256, SMEM_A>>>(
        x, w16, m1b1, w16 + 65536, m1b2, g1, be1, xproj);
    // 2. K/V (t<15) + router projection
    kvr_kernel<<<138, 256, SMEM_KV>>>(
        xproj, w_k, b_k, w_v, b_v, router, w_router, b_router, k15, v15, rproj);
    // 3. buffer attention
    buffer_warp<<<320, 256>>>(rproj, k15, v15, bufp);
    // 4. M2 = Wq @ buf, c2 = bq . buf
    m2_kernel<<<128, 256>>>(w_q, b_q, bufp, m2p, c2p);
    // 5. scores + recv + mlp2 + LN2 + LN3 + scatter   [64 rows/CTA, occ=2]
    fused_recv_mlp2<<<2048, 256, SMEM_B>>>(
        bufp, xproj, m2p, c2p, w16 + 131072, m2b1, w16 + 196608, m2b2,
        g2, be2, g3, be3, out);
}

// round 13
// speedup vs baseline: 1.0912x; 1.0912x over previous
#include <cuda_runtime.h>
#include <cuda_fp16.h>
#include <math.h>
#include <stdint.h>

typedef unsigned long long ull;
#define CLAMPV 10000.0f

// ---------------- static scratch ----------------
__device__ float g_xproj[16777216];   // [BL*T,128]
__device__ float g_k15[245760];       // [BL][15][128]
__device__ float g_v15[245760];
__device__ float g_rproj[40960];      // [32*10][128]
__device__ float g_buf[163840];       // [BL][2][10][64]
__device__ __half g_w16[262144];      // m1w1|m1w2|m2w1|m2w2 (fp16)
__device__ __half g_m2[524288];       // [BL][128][32] fp16 (Wq @ buf)
__device__ float g_c2[4096];          // [BL][32]  (bq . buf_j)

// ---------------- helpers ----------------
__device__ __forceinline__ float gelu_fast(float x) {
    float u = 0.7978845608f * x * (1.0f + 0.044715f * x * x);
    float t; asm("tanh.approx.f32 %0, %1;" : "=f"(t) : "f"(u));
    return 0.5f * x * (1.0f + t);
}
__device__ __forceinline__ uint32_t su32(const void* p) {
    uint32_t a;
    asm("{ .reg .u64 t; cvta.to.shared.u64 t, %1; cvt.u32.u64 %0, t; }" : "=r"(a) : "l"(p));
    return a;
}
__device__ __forceinline__ ull pack4h(float4 v) {
    unsigned short a = __half_as_ushort(__float2half_rn(v.x));
    unsigned short b = __half_as_ushort(__float2half_rn(v.y));
    unsigned short c = __half_as_ushort(__float2half_rn(v.z));
    unsigned short d = __half_as_ushort(__float2half_rn(v.w));
    return (ull)a | ((ull)b << 16) | ((ull)c << 32) | ((ull)d << 48);
}

// ---------------- tensor-core primitives ----------------
__device__ __forceinline__ void ldmx4(uint32_t* r, uint32_t addr) {
    asm volatile("ldmatrix.sync.aligned.m8n8.x4.shared.b16 {%0,%1,%2,%3}, [%4];"
        : "=r"(r[0]), "=r"(r[1]), "=r"(r[2]), "=r"(r[3]) : "r"(addr));
}
__device__ __forceinline__ void ldmx4t(uint32_t* r, uint32_t addr) {
    asm volatile("ldmatrix.sync.aligned.m8n8.x4.trans.shared.b16 {%0,%1,%2,%3}, [%4];"
        : "=r"(r[0]), "=r"(r[1]), "=r"(r[2]), "=r"(r[3]) : "r"(addr));
}
__device__ __forceinline__ void mma16816(float* c, const uint32_t* a, const uint32_t* b) {
    asm volatile("mma.sync.aligned.m16n8k16.row.col.f32.f16.f16.f32 "
        "{%0,%1,%2,%3}, {%4,%5,%6,%7}, {%8,%9}, {%0,%1,%2,%3};"
        : "+f"(c[0]), "+f"(c[1]), "+f"(c[2]), "+f"(c[3])
        : "r"(a[0]), "r"(a[1]), "r"(a[2]), "r"(a[3]), "r"(b[0]), "r"(b[1]));
}

// ============ weight pre-conversion ============
__global__ void cvt_weights(const float* __restrict__ w1a, const float* __restrict__ w2a,
                            const float* __restrict__ w1b, const float* __restrict__ w2b,
                            __half* __restrict__ o)
{
    int i = blockIdx.x * 256 + threadIdx.x;
    if (i >= 262144) return;
    float v;
    if (i < 65536) v = w1a[i];
    else if (i < 131072) v = w2a[i - 65536];
    else if (i < 196608) v = w1b[i - 131072];
    else v = w2b[i - 196608];
    o[i] = __float2half_rn(v);
}

// ---------------- shared smem layout (64-row tiles, occ=2) ----------------
#define RPITCH 272
#define SM_X   0        // 64*272 = 17408
#define SM_W   17408    // 128*272 = 34816
#define SM_H   52224    // 64*272 = 17408
#define SM_P   69632    // 4*64 float2 = 2048
#define SMEM_A 71680
#define SM_BUF 71680    // 1280 floats
#define SM_C2  76800    // 32 floats
#define SMEM_B 76928

// ======================================================================
// Kernel A: gather x -> MLP1 (fp16 mma) -> +x -> LN(g1) -> xproj
// 64 rows/CTA, 256 threads, 8 warps (2x4 grid of 32x32 tiles), occ=2
// ======================================================================
__global__ __launch_bounds__(256, 2) void fused_mlp1(
    const float* __restrict__ in,
    const __half* __restrict__ w1h, const float* __restrict__ b1,
    const __half* __restrict__ w2h, const float* __restrict__ b2,
    const float* __restrict__ ga, const float* __restrict__ ba,
    float* __restrict__ xproj)
{
    extern __shared__ char smem[];
    const int tid = threadIdx.x;
    const int wid = tid >> 5;
    const int lane = tid & 31;
    const int R0 = blockIdx.x * 64;
    const int bl0 = R0 >> 10;
    const int bI = bl0 >> 5, lI = bl0 & 31, tb0 = R0 & 1023;
    const uint32_t sb = su32(smem);
    float2* part = (float2*)(smem + SM_P);   // [4][64]

    // ---- stage X fp16 (gathered): 64 rows ----
#pragma unroll
    for (int i = 0; i < 8; i++) {
        int idx = tid + i * 256;
        int m = idx >> 5, k4 = (idx & 31) * 4;
        int grow = (((bI << 10) + tb0 + m) << 5) + lI;
        float4 v = *(const float4*)(in + grow * 128 + k4);
        *(ull*)(smem + SM_X + m * RPITCH + k4 * 2) = pack4h(v);
    }

    const int wm = (wid >> 2) * 32;
    const int wn = (wid & 3) * 32;
    const int l4 = lane >> 2, lc = (lane & 3) * 2;
    const uint32_t aoffs = (uint32_t)((((lane >> 3) & 1) * 8 + (lane & 7)) * RPITCH
                                      + (((lane >> 4) & 1) * 8) * 2);

    float o[2][4][4];
#pragma unroll
    for (int ni = 0; ni < 4; ni++) {
        int col = wn + ni * 8 + lc;
        float bv0 = __ldg(&b2[col]), bv1 = __ldg(&b2[col + 1]);
#pragma unroll
        for (int mi = 0; mi < 2; mi++) {
            o[mi][ni][0] = bv0; o[mi][ni][1] = bv1;
            o[mi][ni][2] = bv0; o[mi][ni][3] = bv1;
        }
    }

    for (int ch = 0; ch < 4; ch++) {
        __syncthreads();
#pragma unroll
        for (int i = 0; i < 8; i++) {
            int idx = tid + i * 256;
            int k = idx >> 4, j = idx & 15;
            *(int4*)(smem + SM_W + k * RPITCH + j * 16) =
                *(const int4*)(w1h + k * 512 + ch * 128 + j * 8);
        }
        __syncthreads();

        float h[2][4][4];
#pragma unroll
        for (int ni = 0; ni < 4; ni++) {
            int col = wn + ni * 8 + lc;
            float bv0 = __ldg(&b1[ch * 128 + col]), bv1 = __ldg(&b1[ch * 128 + col + 1]);
#pragma unroll
            for (int mi = 0; mi < 2; mi++) {
                h[mi][ni][0] = bv0; h[mi][ni][1] = bv1;
                h[mi][ni][2] = bv0; h[mi][ni][3] = bv1;
            }
        }
#pragma unroll 2
        for (int ks = 0; ks < 8; ks++) {
            int k0 = ks * 16;
            uint32_t a[2][4], b[8];
#pragma unroll
            for (int mi = 0; mi < 2; mi++)
                ldmx4(a[mi], sb + SM_X + (wm + mi * 16) * RPITCH + k0 * 2 + aoffs);
            ldmx4t(b,     sb + SM_W + k0 * RPITCH + wn * 2 + aoffs);
            ldmx4t(b + 4, sb + SM_W + k0 * RPITCH + (wn + 16) * 2 + aoffs);
#pragma unroll
            for (int mi = 0; mi < 2; mi++)
#pragma unroll
                for (int ni = 0; ni < 4; ni++)
                    mma16816(h[mi][ni], a[mi], b + 2 * ni);
        }
#pragma unroll
        for (int mi = 0; mi < 2; mi++)
#pragma unroll
            for (int ni = 0; ni < 4; ni++) {
                int r_ = wm + mi * 16 + l4;
                int cb = (wn + ni * 8 + lc) * 2;
                unsigned short h0 = __half_as_ushort(__float2half_rn(gelu_fast(h[mi][ni][0])));
                unsigned short h1 = __half_as_ushort(__float2half_rn(gelu_fast(h[mi][ni][1])));
                unsigned short h2 = __half_as_ushort(__float2half_rn(gelu_fast(h[mi][ni][2])));
                unsigned short h3 = __half_as_ushort(__float2half_rn(gelu_fast(h[mi][ni][3])));
                *(uint32_t*)(smem + SM_H + r_ * RPITCH + cb) = (uint32_t)h0 | ((uint32_t)h1 << 16);
                *(uint32_t*)(smem + SM_H + (r_ + 8) * RPITCH + cb) = (uint32_t)h2 | ((uint32_t)h3 << 16);
            }
        __syncthreads();
#pragma unroll
        for (int i = 0; i < 8; i++) {
            int idx = tid + i * 256;
            int k = idx >> 4, j = idx & 15;
            *(int4*)(smem + SM_W + k * RPITCH + j * 16) =
                *(const int4*)(w2h + (ch * 128 + k) * 128 + j * 8);
        }
        __syncthreads();
#pragma unroll 2
        for (int ks = 0; ks < 8; ks++) {
            int k0 = ks * 16;
            uint32_t a[2][4], b[8];
#pragma unroll
            for (int mi = 0; mi < 2; mi++)
                ldmx4(a[mi], sb + SM_H + (wm + mi * 16) * RPITCH + k0 * 2 + aoffs);
            ldmx4t(b,     sb + SM_W + k0 * RPITCH + wn * 2 + aoffs);
            ldmx4t(b + 4, sb + SM_W + k0 * RPITCH + (wn + 16) * 2 + aoffs);
#pragma unroll
            for (int mi = 0; mi < 2; mi++)
#pragma unroll
                for (int ni = 0; ni < 4; ni++)
                    mma16816(o[mi][ni], a[mi], b + 2 * ni);
        }
    }

    // ---- epilogue: dump -> +x -> LN -> xproj ----
    __syncthreads();
    float* OB = (float*)(smem);                // [64][132]
#pragma unroll
    for (int mi = 0; mi < 2; mi++)
#pragma unroll
        for (int ni = 0; ni < 4; ni++) {
            int r_ = wm + mi * 16 + l4;
            int c_ = wn + ni * 8 + lc;
            *(float2*)(OB + r_ * 132 + c_) = make_float2(o[mi][ni][0], o[mi][ni][1]);
            *(float2*)(OB + (r_ + 8) * 132 + c_) = make_float2(o[mi][ni][2], o[mi][ni][3]);
        }
    __syncthreads();

    const int m = tid & 63, cq = tid >> 6;
    const int c0 = cq * 32;
    float v[32];
    {
        int grow = (((bI << 10) + tb0 + m) << 5) + lI;
        const float* rp = in + grow * 128 + c0;
#pragma unroll
        for (int g = 0; g < 8; g++) {
            float4 u = *(const float4*)(rp + 4 * g);
            float4 a = *(const float4*)(OB + m * 132 + c0 + 4 * g);
            v[4 * g + 0] = a.x + u.x; v[4 * g + 1] = a.y + u.y;
            v[4 * g + 2] = a.z + u.z; v[4 * g + 3] = a.w + u.w;
        }
    }
    {
        float s = 0.f, q = 0.f;
#pragma unroll
        for (int j = 0; j < 32; j++) { s += v[j]; q += v[j] * v[j]; }
        part[cq * 64 + m] = make_float2(s, q);
    }
    __syncthreads();
    {
        float s = 0.f, q = 0.f;
#pragma unroll
        for (int p_ = 0; p_ < 4; p_++) {
            float2 pp = part[p_ * 64 + m];
            s += pp.x; q += pp.y;
        }
        float mean = s * 0.0078125f;
        float rstd = rsqrtf(fmaxf(q * 0.0078125f - mean * mean, 0.f) + 1e-5f);
#pragma unroll
        for (int j = 0; j < 32; j++)
            v[j] = (v[j] - mean) * rstd * __ldg(&ga[c0 + j]) + __ldg(&ba[c0 + j]);
    }
    const int Rg = R0 + m;
#pragma unroll
    for (int g = 0; g < 8; g++)
        *(float4*)(xproj + Rg * 128 + c0 + 4 * g) =
            make_float4(v[4 * g], v[4 * g + 1], v[4 * g + 2], v[4 * g + 3]);
}

// ======================================================================
// Kernel B: scores via M2 (mma) -> softmax/recv -> MLP2 -> +xproj
//           -> LN(g2) -> LN(g3) -> scatter. 64 rows/CTA, occ=2.
// ======================================================================
__global__ __launch_bounds__(256, 2) void fused_recv_mlp2(
    const float* __restrict__ bufp, const float* __restrict__ xproj,
    const __half* __restrict__ m2, const float* __restrict__ c2,
    const __half* __restrict__ w1h, const float* __restrict__ b1,
    const __half* __restrict__ w2h, const float* __restrict__ b2,
    const float* __restrict__ ga, const float* __restrict__ ba,
    const float* __restrict__ gb, const float* __restrict__ bb,
    float* __restrict__ out)
{
    extern __shared__ char smem[];
    const int tid = threadIdx.x;
    const int wid = tid >> 5;
    const int lane = tid & 31;
    const int R0 = blockIdx.x * 64;
    const int bl0 = R0 >> 10;
    const int bI = bl0 >> 5, lI = bl0 & 31, tb0 = R0 & 1023;
    const uint32_t sb = su32(smem);
    float2* part = (float2*)(smem + SM_P);
    float* BUFS = (float*)(smem + SM_BUF);   // [2][10][64]
    float* C2S  = (float*)(smem + SM_C2);    // [32]
    float* SC   = (float*)(smem + SM_H);     // scores [64][36]

    // ---- stage BUFS, M2 tile (SM_W), c2, xproj fp16 (SM_X) ----
    for (int idx = tid; idx < 1280; idx += 256)
        BUFS[idx] = bufp[bl0 * 1280 + idx];
#pragma unroll
    for (int i = 0; i < 2; i++) {
        int idx = tid + i * 256;
        int k = idx >> 2, seg = idx & 3;
        *(int4*)(smem + SM_W + k * RPITCH + seg * 16) =
            *(const int4*)(m2 + (bl0 << 12) + (k << 5) + seg * 8);
    }
    if (tid < 32) C2S[tid] = c2[(bl0 << 5) + tid];
#pragma unroll
    for (int i = 0; i < 8; i++) {
        int idx = tid + i * 256;
        int m_ = idx >> 5, k4 = (idx & 31) * 4;
        float4 v = *(const float4*)(xproj + (R0 + m_) * 128 + k4);
        *(ull*)(smem + SM_X + m_ * RPITCH + k4 * 2) = pack4h(v);
    }
    __syncthreads();

    const int l4 = lane >> 2, lc = (lane & 3) * 2;
    const uint32_t aoffs = (uint32_t)((((lane >> 3) & 1) * 8 + (lane & 7)) * RPITCH
                                      + (((lane >> 4) & 1) * 8) * 2);

    // ---- score mma: rows 0..63 x [k=128] x [n=32]; warps 0..3 ----
    if (wid < 4) {
        const int wm2 = wid * 16;
        float sc[4][4];
#pragma unroll
        for (int ni = 0; ni < 4; ni++) { sc[ni][0] = sc[ni][1] = sc[ni][2] = sc[ni][3] = 0.f; }
#pragma unroll 2
        for (int ks = 0; ks < 8; ks++) {
            int k0 = ks * 16;
            uint32_t a[4], b[8];
            ldmx4(a, sb + SM_X + wm2 * RPITCH + k0 * 2 + aoffs);
            ldmx4t(b,     sb + SM_W + k0 * RPITCH + aoffs);
            ldmx4t(b + 4, sb + SM_W + k0 * RPITCH + 32 + aoffs);
#pragma unroll
            for (int ni = 0; ni < 4; ni++)
                mma16816(sc[ni], a, b + 2 * ni);
        }
#pragma unroll
        for (int ni = 0; ni < 4; ni++) {
            int n = ni * 8 + lc;
            *(float2*)(SC + (wm2 + l4) * 36 + n)     = make_float2(sc[ni][0], sc[ni][1]);
            *(float2*)(SC + (wm2 + l4 + 8) * 36 + n) = make_float2(sc[ni][2], sc[ni][3]);
        }
    }
    __syncthreads();

    // ---- softmax + recv: thread = (r 0..63, hd, half32) ----
    {
        const int r = tid & 63, hd = (tid >> 6) & 1, hf = tid >> 7;
        const int t = tb0 + r;
        float s[10];
#pragma unroll
        for (int j = 0; j < 10; j++) {
            float sv = (SC[r * 36 + hd * 16 + j] + C2S[hd * 16 + j]) * 0.125f;
            s[j] = fminf(fmaxf(sv, -CLAMPV), CLAMPV);
        }
        bool all = (t >= 10);
        float mx = -1e30f;
#pragma unroll
        for (int j = 0; j < 10; j++) {
            bool a = all || (j >= t - 5 && j <= t + 5);
            if (a) mx = fmaxf(mx, s[j]);
        }
        float p[10], den = 0.f;
#pragma unroll
        for (int j = 0; j < 10; j++) {
            bool a = all || (j >= t - 5 && j <= t + 5);
            p[j] = a ? expf(s[j] - mx) : 0.f;
            den += p[j];
        }
        float rinv = 1.f / den;
#pragma unroll
        for (int j = 0; j < 10; j++) p[j] *= rinv;
        const float* BF = BUFS + hd * 640 + hf * 32;
#pragma unroll
        for (int g = 0; g < 8; g++) {
            float4 acc = make_float4(0.f, 0.f, 0.f, 0.f);
#pragma unroll
            for (int j = 0; j < 10; j++) {
                float4 bv = *(const float4*)(BF + j * 64 + 4 * g);
                acc.x += p[j] * bv.x; acc.y += p[j] * bv.y;
                acc.z += p[j] * bv.z; acc.w += p[j] * bv.w;
            }
            *(ull*)(smem + SM_X + r * RPITCH + (hd * 64 + hf * 32 + 4 * g) * 2) = pack4h(acc);
        }
    }

    const int wm = (wid >> 2) * 32;
    const int wn = (wid & 3) * 32;

    float o[2][4][4];
#pragma unroll
    for (int ni = 0; ni < 4; ni++) {
        int col = wn + ni * 8 + lc;
        float bv0 = __ldg(&b2[col]), bv1 = __ldg(&b2[col + 1]);
#pragma unroll
        for (int mi = 0; mi < 2; mi++) {
            o[mi][ni][0] = bv0; o[mi][ni][1] = bv1;
            o[mi][ni][2] = bv0; o[mi][ni][3] = bv1;
        }
    }

    for (int ch = 0; ch < 4; ch++) {
        __syncthreads();
#pragma unroll
        for (int i = 0; i < 8; i++) {
            int idx = tid + i * 256;
            int k = idx >> 4, j = idx & 15;
            *(int4*)(smem + SM_W + k * RPITCH + j * 16) =
                *(const int4*)(w1h + k * 512 + ch * 128 + j * 8);
        }
        __syncthreads();

        float h[2][4][4];
#pragma unroll
        for (int ni = 0; ni < 4; ni++) {
            int col = wn + ni * 8 + lc;
            float bv0 = __ldg(&b1[ch * 128 + col]), bv1 = __ldg(&b1[ch * 128 + col + 1]);
#pragma unroll
            for (int mi = 0; mi < 2; mi++) {
                h[mi][ni][0] = bv0; h[mi][ni][1] = bv1;
                h[mi][ni][2] = bv0; h[mi][ni][3] = bv1;
            }
        }
#pragma unroll 2
        for (int ks = 0; ks < 8; ks++) {
            int k0 = ks * 16;
            uint32_t a[2][4], b[8];
#pragma unroll
            for (int mi = 0; mi < 2; mi++)
                ldmx4(a[mi], sb + SM_X + (wm + mi * 16) * RPITCH + k0 * 2 + aoffs);
            ldmx4t(b,     sb + SM_W + k0 * RPITCH + wn * 2 + aoffs);
            ldmx4t(b + 4, sb + SM_W + k0 * RPITCH + (wn + 16) * 2 + aoffs);
#pragma unroll
            for (int mi = 0; mi < 2; mi++)
#pragma unroll
                for (int ni = 0; ni < 4; ni++)
                    mma16816(h[mi][ni], a[mi], b + 2 * ni);
        }
#pragma unroll
        for (int mi = 0; mi < 2; mi++)
#pragma unroll
            for (int ni = 0; ni < 4; ni++) {
                int r_ = wm + mi * 16 + l4;
                int cb = (wn + ni * 8 + lc) * 2;
                unsigned short h0 = __half_as_ushort(__float2half_rn(gelu_fast(h[mi][ni][0])));
                unsigned short h1 = __half_as_ushort(__float2half_rn(gelu_fast(h[mi][ni][1])));
                unsigned short h2 = __half_as_ushort(__float2half_rn(gelu_fast(h[mi][ni][2])));
                unsigned short h3 = __half_as_ushort(__float2half_rn(gelu_fast(h[mi][ni][3])));
                *(uint32_t*)(smem + SM_H + r_ * RPITCH + cb) = (uint32_t)h0 | ((uint32_t)h1 << 16);
                *(uint32_t*)(smem + SM_H + (r_ + 8) * RPITCH + cb) = (uint32_t)h2 | ((uint32_t)h3 << 16);
            }
        __syncthreads();
#pragma unroll
        for (int i = 0; i < 8; i++) {
            int idx = tid + i * 256;
            int k = idx >> 4, j = idx & 15;
            *(int4*)(smem + SM_W + k * RPITCH + j * 16) =
                *(const int4*)(w2h + (ch * 128 + k) * 128 + j * 8);
        }
        __syncthreads();
#pragma unroll 2
        for (int ks = 0; ks < 8; ks++) {
            int k0 = ks * 16;
            uint32_t a[2][4], b[8];
#pragma unroll
            for (int mi = 0; mi < 2; mi++)
                ldmx4(a[mi], sb + SM_H + (wm + mi * 16) * RPITCH + k0 * 2 + aoffs);
            ldmx4t(b,     sb + SM_W + k0 * RPITCH + wn * 2 + aoffs);
            ldmx4t(b + 4, sb + SM_W + k0 * RPITCH + (wn + 16) * 2 + aoffs);
#pragma unroll
            for (int mi = 0; mi < 2; mi++)
#pragma unroll
                for (int ni = 0; ni < 4; ni++)
                    mma16816(o[mi][ni], a[mi], b + 2 * ni);
        }
    }

    // ---- epilogue: +xproj, LN(g2), LN(g3), scatter ----
    __syncthreads();
    float* OB = (float*)(smem);                // [64][132]
#pragma unroll
    for (int mi = 0; mi < 2; mi++)
#pragma unroll
        for (int ni = 0; ni < 4; ni++) {
            int r_ = wm + mi * 16 + l4;
            int c_ = wn + ni * 8 + lc;
            *(float2*)(OB + r_ * 132 + c_) = make_float2(o[mi][ni][0], o[mi][ni][1]);
            *(float2*)(OB + (r_ + 8) * 132 + c_) = make_float2(o[mi][ni][2], o[mi][ni][3]);
        }
    __syncthreads();

    const int m = tid & 63, cq = tid >> 6;
    const int c0 = cq * 32;
    float v[32];
    {
        const float* rp = xproj + (R0 + m) * 128 + c0;
#pragma unroll
        for (int g = 0; g < 8; g++) {
            float4 u = *(const float4*)(rp + 4 * g);
            float4 a = *(const float4*)(OB + m * 132 + c0 + 4 * g);
            v[4 * g + 0] = a.x + u.x; v[4 * g + 1] = a.y + u.y;
            v[4 * g + 2] = a.z + u.z; v[4 * g + 3] = a.w + u.w;
        }
    }
    {
        float s = 0.f, q = 0.f;
#pragma unroll
        for (int j = 0; j < 32; j++) { s += v[j]; q += v[j] * v[j]; }
        part[cq * 64 + m] = make_float2(s, q);
    }
    __syncthreads();
    {
        float s = 0.f, q = 0.f;
#pragma unroll
        for (int p_ = 0; p_ < 4; p_++) {
            float2 pp = part[p_ * 64 + m];
            s += pp.x; q += pp.y;
        }
        float mean = s * 0.0078125f;
        float rstd = rsqrtf(fmaxf(q * 0.0078125f - mean * mean, 0.f) + 1e-5f);
#pragma unroll
        for (int j = 0; j < 32; j++)
            v[j] = (v[j] - mean) * rstd * __ldg(&ga[c0 + j]) + __ldg(&ba[c0 + j]);
    }
    __syncthreads();
    {
        float s = 0.f, q = 0.f;
#pragma unroll
        for (int j = 0; j < 32; j++) { s += v[j]; q += v[j] * v[j]; }
        part[cq * 64 + m] = make_float2(s, q);
    }
    __syncthreads();
    float s = 0.f, q = 0.f;
#pragma unroll
    for (int p_ = 0; p_ < 4; p_++) {
        float2 pp = part[p_ * 64 + m];
        s += pp.x; q += pp.y;
    }
    float m2v = s * 0.0078125f;
    float rstd2 = rsqrtf(fmaxf(q * 0.0078125f - m2v * m2v, 0.f) + 1e-5f);
    int t = tb0 + m;
    int ob = (((bI << 10) + t) * 32 + lI) * 128 + c0;
#pragma unroll
    for (int g = 0; g < 8; g++) {
        float4 w;
        w.x = (v[4 * g + 0] - m2v) * rstd2 * __ldg(&gb[c0 + 4 * g + 0]) + __ldg(&bb[c0 + 4 * g + 0]);
        w.y = (v[4 * g + 1] - m2v) * rstd2 * __ldg(&gb[c0 + 4 * g + 1]) + __ldg(&bb[c0 + 4 * g + 1]);
        w.z = (v[4 * g + 2] - m2v) * rstd2 * __ldg(&gb[c0 + 4 * g + 2]) + __ldg(&bb[c0 + 4 * g + 2]);
        w.w = (v[4 * g + 3] - m2v) * rstd2 * __ldg(&gb[c0 + 4 * g + 3]) + __ldg(&bb[c0 + 4 * g + 3]);
        *(float4*)(out + ob + 4 * g) = w;
    }
}

// ============ merged K/V projection (blocks 0..127) + router proj (128..137) ============
#define SMEM_KV (34688 * 4)
__global__ __launch_bounds__(256, 1) void kvr_kernel(
    const float* __restrict__ xp,
    const float* __restrict__ wk, const float* __restrict__ bk,
    const float* __restrict__ wv, const float* __restrict__ bv,
    const float* __restrict__ router, const float* __restrict__ wr, const float* __restrict__ br,
    float* __restrict__ k15, float* __restrict__ v15, float* __restrict__ rp)
{
    extern __shared__ float sm[];
    const int tid = threadIdx.x;
    if (blockIdx.x < 128) {
        float* Xs = sm;
        float* Wks = sm + 1920;
        float* Wvs = sm + 18304;
        const int bl = blockIdx.x;
        for (int idx = tid; idx < 1920; idx += 256)
            Xs[idx] = xp[(bl * 1024 + (idx >> 7)) * 128 + (idx & 127)];
        for (int idx = tid; idx < 16384; idx += 256) { Wks[idx] = wk[idx]; Wvs[idx] = wv[idx]; }
        __syncthreads();
        const int m = tid >> 7, n = tid & 127;
        const float* W = m ? Wvs : Wks;
        const float bsv = m ? __ldg(&bv[n]) : __ldg(&bk[n]);
        float* o = m ? v15 : k15;
        for (int t = 0; t < 15; t++) {
            float acc = bsv;
#pragma unroll 8
            for (int k = 0; k < 128; k++) acc += Xs[t * 128 + k] * W[k * 128 + n];
            o[(bl * 15 + t) * 128 + n] = acc;
        }
    } else {
        float* Ws = sm;
        float* Rs = sm + 16384;
        const int row0 = (blockIdx.x - 128) * 32;
        for (int idx = tid; idx < 16384; idx += 256) Ws[idx] = wr[idx];
        for (int idx = tid; idx < 4096; idx += 256)
            Rs[idx] = router[(row0 + (idx >> 7)) * 128 + (idx & 127)];
        __syncthreads();
        const int n = tid & 127, rbase = (tid >> 7) * 16;
        const float bb_ = __ldg(&br[n]);
        for (int rr = 0; rr < 16; rr++) {
            int r = rbase + rr;
            float acc = bb_;
#pragma unroll 8
            for (int k = 0; k < 128; k++) acc += Rs[r * 128 + k] * Ws[k * 128 + n];
            rp[(row0 + r) * 128 + n] = acc;
        }
    }
}

// ============ buffer attention: warp per (bl, h, i) ============
__global__ __launch_bounds__(256) void buffer_warp(
    const float* __restrict__ rp, const float* __restrict__ k15,
    const float* __restrict__ v15, float* __restrict__ buf)
{
    const int w = (blockIdx.x << 3) + (threadIdx.x >> 5);
    const int lane = threadIdx.x & 31;
    const int bl = w / 20;
    const int rem = w - bl * 20;
    const int h = rem / 10, i = rem - (rem / 10) * 10;
    const int l = bl & 31;
    const float* q = rp + (l * 10 + i) * 128 + h * 64;
    const float q0 = q[lane], q1 = q[lane + 32];
    const int jlo = (i > 5) ? (i - 5) : 0;
    const int cnt = i + 5 - jlo + 1;
    float s[11];
#pragma unroll
    for (int jj = 0; jj < 11; jj++) {
        float d = 0.f;
        if (jj < cnt) {
            int base = (bl * 15 + jlo + jj) * 128 + h * 64;
            d = q0 * k15[base + lane] + q1 * k15[base + lane + 32];
        }
        d += __shfl_xor_sync(0xffffffffu, d, 16);
        d += __shfl_xor_sync(0xffffffffu, d, 8);
        d += __shfl_xor_sync(0xffffffffu, d, 4);
        d += __shfl_xor_sync(0xffffffffu, d, 2);
        d += __shfl_xor_sync(0xffffffffu, d, 1);
        s[jj] = fminf(fmaxf(d * 0.125f, -CLAMPV), CLAMPV);
    }
    float mx = -1e30f;
#pragma unroll
    for (int jj = 0; jj < 11; jj++) if (jj < cnt) mx = fmaxf(mx, s[jj]);
    float den = 0.f, o0 = 0.f, o1 = 0.f;
#pragma unroll
    for (int jj = 0; jj < 11; jj++) {
        if (jj < cnt) {
            float p = expf(s[jj] - mx);
            den += p;
            int vbase = (bl * 15 + jlo + jj) * 128 + h * 64;
            o0 += p * v15[vbase + lane];
            o1 += p * v15[vbase + lane + 32];
        }
    }
    float rinv = 1.f / den;
    int ob = ((bl * 2 + h) * 10 + i) * 64;
    buf[ob + lane] = o0 * rinv;
    buf[ob + lane + 32] = o1 * rinv;
}

// ============ M2 = Wq @ buf^T per (bl), fp16; c2 = bq . buf ============
__global__ __launch_bounds__(256) void m2_kernel(
    const float* __restrict__ wq, const float* __restrict__ bq,
    const float* __restrict__ bufp, __half* __restrict__ m2, float* __restrict__ c2)
{
    __shared__ float bufS[1280];
    const int bl = blockIdx.x, tid = threadIdx.x;
    for (int idx = tid; idx < 1280; idx += 256) bufS[idx] = bufp[bl * 1280 + idx];
    __syncthreads();
    const int n = tid & 31, h = n >> 4, j = n & 15;
    const float* bv = bufS + h * 640 + j * 64;
#pragma unroll 1
    for (int it = 0; it < 16; it++) {
        int k = (tid >> 5) + (it << 3);
        float acc = 0.f;
        if (j < 10) {
            const float* wr = wq + k * 128 + h * 64;
#pragma unroll 8
            for (int d = 0; d < 64; d++) acc += wr[d] * bv[d];
        }
        m2[(bl << 12) + (k << 5) + n] = __float2half_rn(acc);
    }
    if (tid < 32) {
        float c = 0.f;
        if (j < 10) {
            const float* br_ = bq + h * 64;
#pragma unroll 8
            for (int d = 0; d < 64; d++) c += br_[d] * bv[d];
        }
        c2[(bl << 5) + tid] = c;
    }
}

// ============ launch ============
extern "C" void kernel_launch(void* const* d_in, const int* in_sizes, int n_in,
                              void* d_out, int out_size)
{
    const float* x        = (const float*)d_in[0];
    const float* router   = (const float*)d_in[1];
    const float* w_router = (const float*)d_in[2];
    const float* b_router = (const float*)d_in[3];
    const float* w_k      = (const float*)d_in[4];
    const float* b_k      = (const float*)d_in[5];
    const float* w_v      = (const float*)d_in[6];
    const float* b_v      = (const float*)d_in[7];
    const float* w_q      = (const float*)d_in[8];
    const float* b_q      = (const float*)d_in[9];
    const float* m1w1 = (const float*)d_in[10];
    const float* m1b1 = (const float*)d_in[11];
    const float* m1w2 = (const float*)d_in[12];
    const float* m1b2 = (const float*)d_in[13];
    const float* m2w1 = (const float*)d_in[14];
    const float* m2b1 = (const float*)d_in[15];
    const float* m2w2 = (const float*)d_in[16];
    const float* m2b2 = (const float*)d_in[17];
    const float* g1  = (const float*)d_in[18];
    const float* be1 = (const float*)d_in[19];
    const float* g2  = (const float*)d_in[20];
    const float* be2 = (const float*)d_in[21];
    const float* g3  = (const float*)d_in[22];
    const float* be3 = (const float*)d_in[23];
    float* out = (float*)d_out;

    float *xproj, *k15, *v15, *rproj, *bufp, *c2p;
    __half *w16, *m2p;
    cudaGetSymbolAddress((void**)&xproj, g_xproj);
    cudaGetSymbolAddress((void**)&k15,   g_k15);
    cudaGetSymbolAddress((void**)&v15,   g_v15);
    cudaGetSymbolAddress((void**)&rproj, g_rproj);
    cudaGetSymbolAddress((void**)&bufp,  g_buf);
    cudaGetSymbolAddress((void**)&w16,   g_w16);
    cudaGetSymbolAddress((void**)&m2p,   g_m2);
    cudaGetSymbolAddress((void**)&c2p,   g_c2);

    cudaFuncSetAttribute(fused_mlp1, cudaFuncAttributeMaxDynamicSharedMemorySize, SMEM_A);
    cudaFuncSetAttribute(fused_recv_mlp2, cudaFuncAttributeMaxDynamicSharedMemorySize, SMEM_B);
    cudaFuncSetAttribute(kvr_kernel, cudaFuncAttributeMaxDynamicSharedMemorySize, SMEM_KV);

    // 0. weights -> fp16
    cvt_weights<<<1024, 256>>>(m1w1, m1w2, m2w1, m2w2, w16);
    // 1. x_proj = LN(x + mlp1(x))   [64 rows/CTA, occ=2]
    fused_mlp1<<<2048, 256, SMEM_A>>>(
        x, w16, m1b1, w16 + 65536, m1b2, g1, be1, xproj);
    // 2. K/V (t<15) + router projection
    kvr_kernel<<<138, 256, SMEM_KV>>>(
        xproj, w_k, b_k, w_v, b_v, router, w_router, b_router, k15, v15, rproj);
    // 3. buffer attention
    buffer_warp<<<320, 256>>>(rproj, k15, v15, bufp);
    // 4. M2 = Wq @ buf, c2 = bq . buf
    m2_kernel<<<128, 256>>>(w_q, b_q, bufp, m2p, c2p);
    // 5. scores + recv + mlp2 + LN2 + LN3 + scatter   [64 rows/CTA, occ=2]
    fused_recv_mlp2<<<2048, 256, SMEM_B>>>(
        bufp, xproj, m2p, c2p, w16 + 131072, m2b1, w16 + 196608, m2b2,
        g2, be2, g3, be3, out);
}

// round 14
// speedup vs baseline: 1.0928x; 1.0014x over previous
#include <cuda_runtime.h>
#include <cuda_fp16.h>
#include <math.h>
#include <stdint.h>

typedef unsigned long long ull;
#define CLAMPV 10000.0f

// ---------------- static scratch ----------------
__device__ float g_xproj[16777216];   // [BL*T,128]
__device__ float g_k15[245760];       // [BL][15][128]
__device__ float g_v15[245760];
__device__ float g_rproj[40960];      // [32*10][128]
__device__ float g_buf[163840];       // [BL][2][10][64]
__device__ __half g_w16[262144];      // m1w1|m1w2|m2w1|m2w2 (fp16)
__device__ __half g_m2[524288];       // [BL][128][32] fp16 (Wq @ buf)
__device__ float g_c2[4096];          // [BL][32]  (bq . buf_j)

// ---------------- helpers ----------------
__device__ __forceinline__ float gelu_fast(float x) {
    float u = 0.7978845608f * x * (1.0f + 0.044715f * x * x);
    float t; asm("tanh.approx.f32 %0, %1;" : "=f"(t) : "f"(u));
    return 0.5f * x * (1.0f + t);
}
__device__ __forceinline__ uint32_t su32(const void* p) {
    uint32_t a;
    asm("{ .reg .u64 t; cvta.to.shared.u64 t, %1; cvt.u32.u64 %0, t; }" : "=r"(a) : "l"(p));
    return a;
}
__device__ __forceinline__ ull pack4h(float4 v) {
    unsigned short a = __half_as_ushort(__float2half_rn(v.x));
    unsigned short b = __half_as_ushort(__float2half_rn(v.y));
    unsigned short c = __half_as_ushort(__float2half_rn(v.z));
    unsigned short d = __half_as_ushort(__float2half_rn(v.w));
    return (ull)a | ((ull)b << 16) | ((ull)c << 32) | ((ull)d << 48);
}

// ---------------- tensor-core primitives ----------------
__device__ __forceinline__ void ldmx4(uint32_t* r, uint32_t addr) {
    asm volatile("ldmatrix.sync.aligned.m8n8.x4.shared.b16 {%0,%1,%2,%3}, [%4];"
        : "=r"(r[0]), "=r"(r[1]), "=r"(r[2]), "=r"(r[3]) : "r"(addr));
}
__device__ __forceinline__ void ldmx4t(uint32_t* r, uint32_t addr) {
    asm volatile("ldmatrix.sync.aligned.m8n8.x4.trans.shared.b16 {%0,%1,%2,%3}, [%4];"
        : "=r"(r[0]), "=r"(r[1]), "=r"(r[2]), "=r"(r[3]) : "r"(addr));
}
__device__ __forceinline__ void mma16816(float* c, const uint32_t* a, const uint32_t* b) {
    asm volatile("mma.sync.aligned.m16n8k16.row.col.f32.f16.f16.f32 "
        "{%0,%1,%2,%3}, {%4,%5,%6,%7}, {%8,%9}, {%0,%1,%2,%3};"
        : "+f"(c[0]), "+f"(c[1]), "+f"(c[2]), "+f"(c[3])
        : "r"(a[0]), "r"(a[1]), "r"(a[2]), "r"(a[3]), "r"(b[0]), "r"(b[1]));
}

// ============ weight pre-conversion ============
__global__ void cvt_weights(const float* __restrict__ w1a, const float* __restrict__ w2a,
                            const float* __restrict__ w1b, const float* __restrict__ w2b,
                            __half* __restrict__ o)
{
    int i = blockIdx.x * 256 + threadIdx.x;
    if (i >= 262144) return;
    float v;
    if (i < 65536) v = w1a[i];
    else if (i < 131072) v = w2a[i - 65536];
    else if (i < 196608) v = w1b[i - 131072];
    else v = w2b[i - 196608];
    o[i] = __float2half_rn(v);
}

// ---------------- shared smem layout (64-row tiles, occ=2) ----------------
#define RPITCH 272
#define SM_X   0        // 64*272 = 17408
#define SM_W   17408    // 128*272 = 34816
#define SM_H   52224    // 64*272 = 17408
#define SM_P   69632    // 4*64 float2 = 2048
#define SMEM_A 71680
#define SM_BUF 71680    // 1280 floats
#define SM_C2  76800    // 32 floats
#define SMEM_B 76928

// ======================================================================
// Kernel A: gather x -> MLP1 (fp16 mma) -> +x -> LN(g1) -> xproj
// 64 rows/CTA, 256 threads, 8 warps (2x4 grid of 32x32 tiles), occ=2
// ======================================================================
__global__ __launch_bounds__(256, 2) void fused_mlp1(
    const float* __restrict__ in,
    const __half* __restrict__ w1h, const float* __restrict__ b1,
    const __half* __restrict__ w2h, const float* __restrict__ b2,
    const float* __restrict__ ga, const float* __restrict__ ba,
    float* __restrict__ xproj)
{
    extern __shared__ char smem[];
    const int tid = threadIdx.x;
    const int wid = tid >> 5;
    const int lane = tid & 31;
    const int R0 = blockIdx.x * 64;
    const int bl0 = R0 >> 10;
    const int bI = bl0 >> 5, lI = bl0 & 31, tb0 = R0 & 1023;
    const uint32_t sb = su32(smem);
    float2* part = (float2*)(smem + SM_P);   // [4][64]

    // ---- stage X fp16 (gathered): 64 rows ----
#pragma unroll
    for (int i = 0; i < 8; i++) {
        int idx = tid + i * 256;
        int m = idx >> 5, k4 = (idx & 31) * 4;
        int grow = (((bI << 10) + tb0 + m) << 5) + lI;
        float4 v = *(const float4*)(in + grow * 128 + k4);
        *(ull*)(smem + SM_X + m * RPITCH + k4 * 2) = pack4h(v);
    }

    const int wm = (wid >> 2) * 32;
    const int wn = (wid & 3) * 32;
    const int l4 = lane >> 2, lc = (lane & 3) * 2;
    const uint32_t aoffs = (uint32_t)((((lane >> 3) & 1) * 8 + (lane & 7)) * RPITCH
                                      + (((lane >> 4) & 1) * 8) * 2);

    float o[2][4][4];
#pragma unroll
    for (int ni = 0; ni < 4; ni++) {
        int col = wn + ni * 8 + lc;
        float bv0 = __ldg(&b2[col]), bv1 = __ldg(&b2[col + 1]);
#pragma unroll
        for (int mi = 0; mi < 2; mi++) {
            o[mi][ni][0] = bv0; o[mi][ni][1] = bv1;
            o[mi][ni][2] = bv0; o[mi][ni][3] = bv1;
        }
    }

    for (int ch = 0; ch < 4; ch++) {
        __syncthreads();
#pragma unroll
        for (int i = 0; i < 8; i++) {
            int idx = tid + i * 256;
            int k = idx >> 4, j = idx & 15;
            *(int4*)(smem + SM_W + k * RPITCH + j * 16) =
                *(const int4*)(w1h + k * 512 + ch * 128 + j * 8);
        }
        __syncthreads();

        float h[2][4][4];
#pragma unroll
        for (int ni = 0; ni < 4; ni++) {
            int col = wn + ni * 8 + lc;
            float bv0 = __ldg(&b1[ch * 128 + col]), bv1 = __ldg(&b1[ch * 128 + col + 1]);
#pragma unroll
            for (int mi = 0; mi < 2; mi++) {
                h[mi][ni][0] = bv0; h[mi][ni][1] = bv1;
                h[mi][ni][2] = bv0; h[mi][ni][3] = bv1;
            }
        }
#pragma unroll 2
        for (int ks = 0; ks < 8; ks++) {
            int k0 = ks * 16;
            uint32_t a[2][4], b[8];
#pragma unroll
            for (int mi = 0; mi < 2; mi++)
                ldmx4(a[mi], sb + SM_X + (wm + mi * 16) * RPITCH + k0 * 2 + aoffs);
            ldmx4t(b,     sb + SM_W + k0 * RPITCH + wn * 2 + aoffs);
            ldmx4t(b + 4, sb + SM_W + k0 * RPITCH + (wn + 16) * 2 + aoffs);
#pragma unroll
            for (int mi = 0; mi < 2; mi++)
#pragma unroll
                for (int ni = 0; ni < 4; ni++)
                    mma16816(h[mi][ni], a[mi], b + 2 * ni);
        }
#pragma unroll
        for (int mi = 0; mi < 2; mi++)
#pragma unroll
            for (int ni = 0; ni < 4; ni++) {
                int r_ = wm + mi * 16 + l4;
                int cb = (wn + ni * 8 + lc) * 2;
                unsigned short h0 = __half_as_ushort(__float2half_rn(gelu_fast(h[mi][ni][0])));
                unsigned short h1 = __half_as_ushort(__float2half_rn(gelu_fast(h[mi][ni][1])));
                unsigned short h2 = __half_as_ushort(__float2half_rn(gelu_fast(h[mi][ni][2])));
                unsigned short h3 = __half_as_ushort(__float2half_rn(gelu_fast(h[mi][ni][3])));
                *(uint32_t*)(smem + SM_H + r_ * RPITCH + cb) = (uint32_t)h0 | ((uint32_t)h1 << 16);
                *(uint32_t*)(smem + SM_H + (r_ + 8) * RPITCH + cb) = (uint32_t)h2 | ((uint32_t)h3 << 16);
            }
        __syncthreads();
#pragma unroll
        for (int i = 0; i < 8; i++) {
            int idx = tid + i * 256;
            int k = idx >> 4, j = idx & 15;
            *(int4*)(smem + SM_W + k * RPITCH + j * 16) =
                *(const int4*)(w2h + (ch * 128 + k) * 128 + j * 8);
        }
        __syncthreads();
#pragma unroll 2
        for (int ks = 0; ks < 8; ks++) {
            int k0 = ks * 16;
            uint32_t a[2][4], b[8];
#pragma unroll
            for (int mi = 0; mi < 2; mi++)
                ldmx4(a[mi], sb + SM_H + (wm + mi * 16) * RPITCH + k0 * 2 + aoffs);
            ldmx4t(b,     sb + SM_W + k0 * RPITCH + wn * 2 + aoffs);
            ldmx4t(b + 4, sb + SM_W + k0 * RPITCH + (wn + 16) * 2 + aoffs);
#pragma unroll
            for (int mi = 0; mi < 2; mi++)
#pragma unroll
                for (int ni = 0; ni < 4; ni++)
                    mma16816(o[mi][ni], a[mi], b + 2 * ni);
        }
    }

    // ---- epilogue: dump -> +x -> LN -> xproj ----
    __syncthreads();
    float* OB = (float*)(smem);                // [64][132]
#pragma unroll
    for (int mi = 0; mi < 2; mi++)
#pragma unroll
        for (int ni = 0; ni < 4; ni++) {
            int r_ = wm + mi * 16 + l4;
            int c_ = wn + ni * 8 + lc;
            *(float2*)(OB + r_ * 132 + c_) = make_float2(o[mi][ni][0], o[mi][ni][1]);
            *(float2*)(OB + (r_ + 8) * 132 + c_) = make_float2(o[mi][ni][2], o[mi][ni][3]);
        }
    __syncthreads();

    const int m = tid & 63, cq = tid >> 6;
    const int c0 = cq * 32;
    float v[32];
    {
        int grow = (((bI << 10) + tb0 + m) << 5) + lI;
        const float* rp = in + grow * 128 + c0;
#pragma unroll
        for (int g = 0; g < 8; g++) {
            float4 u = *(const float4*)(rp + 4 * g);
            float4 a = *(const float4*)(OB + m * 132 + c0 + 4 * g);
            v[4 * g + 0] = a.x + u.x; v[4 * g + 1] = a.y + u.y;
            v[4 * g + 2] = a.z + u.z; v[4 * g + 3] = a.w + u.w;
        }
    }
    {
        float s = 0.f, q = 0.f;
#pragma unroll
        for (int j = 0; j < 32; j++) { s += v[j]; q += v[j] * v[j]; }
        part[cq * 64 + m] = make_float2(s, q);
    }
    __syncthreads();
    {
        float s = 0.f, q = 0.f;
#pragma unroll
        for (int p_ = 0; p_ < 4; p_++) {
            float2 pp = part[p_ * 64 + m];
            s += pp.x; q += pp.y;
        }
        float mean = s * 0.0078125f;
        float rstd = rsqrtf(fmaxf(q * 0.0078125f - mean * mean, 0.f) + 1e-5f);
#pragma unroll
        for (int j = 0; j < 32; j++)
            v[j] = (v[j] - mean) * rstd * __ldg(&ga[c0 + j]) + __ldg(&ba[c0 + j]);
    }
    const int Rg = R0 + m;
#pragma unroll
    for (int g = 0; g < 8; g++)
        *(float4*)(xproj + Rg * 128 + c0 + 4 * g) =
            make_float4(v[4 * g], v[4 * g + 1], v[4 * g + 2], v[4 * g + 3]);
}

// ======================================================================
// Kernel B: scores via M2 (mma) -> softmax/recv -> MLP2 -> +xproj
//           -> LN(g2) -> LN(g3) -> scatter. 64 rows/CTA, occ=2.
// ======================================================================
__global__ __launch_bounds__(256, 2) void fused_recv_mlp2(
    const float* __restrict__ bufp, const float* __restrict__ xproj,
    const __half* __restrict__ m2, const float* __restrict__ c2,
    const __half* __restrict__ w1h, const float* __restrict__ b1,
    const __half* __restrict__ w2h, const float* __restrict__ b2,
    const float* __restrict__ ga, const float* __restrict__ ba,
    const float* __restrict__ gb, const float* __restrict__ bb,
    float* __restrict__ out)
{
    extern __shared__ char smem[];
    const int tid = threadIdx.x;
    const int wid = tid >> 5;
    const int lane = tid & 31;
    const int R0 = blockIdx.x * 64;
    const int bl0 = R0 >> 10;
    const int bI = bl0 >> 5, lI = bl0 & 31, tb0 = R0 & 1023;
    const uint32_t sb = su32(smem);
    float2* part = (float2*)(smem + SM_P);
    float* BUFS = (float*)(smem + SM_BUF);   // [2][10][64]
    float* C2S  = (float*)(smem + SM_C2);    // [32]
    float* SC   = (float*)(smem + SM_H);     // scores [64][36]

    // ---- stage BUFS, M2 tile (SM_W), c2, xproj fp16 (SM_X) ----
    for (int idx = tid; idx < 1280; idx += 256)
        BUFS[idx] = bufp[bl0 * 1280 + idx];
#pragma unroll
    for (int i = 0; i < 2; i++) {
        int idx = tid + i * 256;
        int k = idx >> 2, seg = idx & 3;
        *(int4*)(smem + SM_W + k * RPITCH + seg * 16) =
            *(const int4*)(m2 + (bl0 << 12) + (k << 5) + seg * 8);
    }
    if (tid < 32) C2S[tid] = c2[(bl0 << 5) + tid];
#pragma unroll
    for (int i = 0; i < 8; i++) {
        int idx = tid + i * 256;
        int m_ = idx >> 5, k4 = (idx & 31) * 4;
        float4 v = *(const float4*)(xproj + (R0 + m_) * 128 + k4);
        *(ull*)(smem + SM_X + m_ * RPITCH + k4 * 2) = pack4h(v);
    }
    __syncthreads();

    const int l4 = lane >> 2, lc = (lane & 3) * 2;
    const uint32_t aoffs = (uint32_t)((((lane >> 3) & 1) * 8 + (lane & 7)) * RPITCH
                                      + (((lane >> 4) & 1) * 8) * 2);

    // ---- score mma: rows 0..63 x [k=128] x [n=32]; warps 0..3 ----
    if (wid < 4) {
        const int wm2 = wid * 16;
        float sc[4][4];
#pragma unroll
        for (int ni = 0; ni < 4; ni++) { sc[ni][0] = sc[ni][1] = sc[ni][2] = sc[ni][3] = 0.f; }
#pragma unroll 2
        for (int ks = 0; ks < 8; ks++) {
            int k0 = ks * 16;
            uint32_t a[4], b[8];
            ldmx4(a, sb + SM_X + wm2 * RPITCH + k0 * 2 + aoffs);
            ldmx4t(b,     sb + SM_W + k0 * RPITCH + aoffs);
            ldmx4t(b + 4, sb + SM_W + k0 * RPITCH + 32 + aoffs);
#pragma unroll
            for (int ni = 0; ni < 4; ni++)
                mma16816(sc[ni], a, b + 2 * ni);
        }
#pragma unroll
        for (int ni = 0; ni < 4; ni++) {
            int n = ni * 8 + lc;
            *(float2*)(SC + (wm2 + l4) * 36 + n)     = make_float2(sc[ni][0], sc[ni][1]);
            *(float2*)(SC + (wm2 + l4 + 8) * 36 + n) = make_float2(sc[ni][2], sc[ni][3]);
        }
    }
    __syncthreads();

    // ---- softmax + recv: thread = (r 0..63, hd, half32) ----
    {
        const int r = tid & 63, hd = (tid >> 6) & 1, hf = tid >> 7;
        const int t = tb0 + r;
        float s[10];
#pragma unroll
        for (int j = 0; j < 10; j++) {
            float sv = (SC[r * 36 + hd * 16 + j] + C2S[hd * 16 + j]) * 0.125f;
            s[j] = fminf(fmaxf(sv, -CLAMPV), CLAMPV);
        }
        bool all = (t >= 10);
        float mx = -1e30f;
#pragma unroll
        for (int j = 0; j < 10; j++) {
            bool a = all || (j >= t - 5 && j <= t + 5);
            if (a) mx = fmaxf(mx, s[j]);
        }
        float p[10], den = 0.f;
#pragma unroll
        for (int j = 0; j < 10; j++) {
            bool a = all || (j >= t - 5 && j <= t + 5);
            p[j] = a ? expf(s[j] - mx) : 0.f;
            den += p[j];
        }
        float rinv = 1.f / den;
#pragma unroll
        for (int j = 0; j < 10; j++) p[j] *= rinv;
        const float* BF = BUFS + hd * 640 + hf * 32;
#pragma unroll
        for (int g = 0; g < 8; g++) {
            float4 acc = make_float4(0.f, 0.f, 0.f, 0.f);
#pragma unroll
            for (int j = 0; j < 10; j++) {
                float4 bv = *(const float4*)(BF + j * 64 + 4 * g);
                acc.x += p[j] * bv.x; acc.y += p[j] * bv.y;
                acc.z += p[j] * bv.z; acc.w += p[j] * bv.w;
            }
            *(ull*)(smem + SM_X + r * RPITCH + (hd * 64 + hf * 32 + 4 * g) * 2) = pack4h(acc);
        }
    }

    const int wm = (wid >> 2) * 32;
    const int wn = (wid & 3) * 32;

    float o[2][4][4];
#pragma unroll
    for (int ni = 0; ni < 4; ni++) {
        int col = wn + ni * 8 + lc;
        float bv0 = __ldg(&b2[col]), bv1 = __ldg(&b2[col + 1]);
#pragma unroll
        for (int mi = 0; mi < 2; mi++) {
            o[mi][ni][0] = bv0; o[mi][ni][1] = bv1;
            o[mi][ni][2] = bv0; o[mi][ni][3] = bv1;
        }
    }

    for (int ch = 0; ch < 4; ch++) {
        __syncthreads();
#pragma unroll
        for (int i = 0; i < 8; i++) {
            int idx = tid + i * 256;
            int k = idx >> 4, j = idx & 15;
            *(int4*)(smem + SM_W + k * RPITCH + j * 16) =
                *(const int4*)(w1h + k * 512 + ch * 128 + j * 8);
        }
        __syncthreads();

        float h[2][4][4];
#pragma unroll
        for (int ni = 0; ni < 4; ni++) {
            int col = wn + ni * 8 + lc;
            float bv0 = __ldg(&b1[ch * 128 + col]), bv1 = __ldg(&b1[ch * 128 + col + 1]);
#pragma unroll
            for (int mi = 0; mi < 2; mi++) {
                h[mi][ni][0] = bv0; h[mi][ni][1] = bv1;
                h[mi][ni][2] = bv0; h[mi][ni][3] = bv1;
            }
        }
#pragma unroll 2
        for (int ks = 0; ks < 8; ks++) {
            int k0 = ks * 16;
            uint32_t a[2][4], b[8];
#pragma unroll
            for (int mi = 0; mi < 2; mi++)
                ldmx4(a[mi], sb + SM_X + (wm + mi * 16) * RPITCH + k0 * 2 + aoffs);
            ldmx4t(b,     sb + SM_W + k0 * RPITCH + wn * 2 + aoffs);
            ldmx4t(b + 4, sb + SM_W + k0 * RPITCH + (wn + 16) * 2 + aoffs);
#pragma unroll
            for (int mi = 0; mi < 2; mi++)
#pragma unroll
                for (int ni = 0; ni < 4; ni++)
                    mma16816(h[mi][ni], a[mi], b + 2 * ni);
        }
#pragma unroll
        for (int mi = 0; mi < 2; mi++)
#pragma unroll
            for (int ni = 0; ni < 4; ni++) {
                int r_ = wm + mi * 16 + l4;
                int cb = (wn + ni * 8 + lc) * 2;
                unsigned short h0 = __half_as_ushort(__float2half_rn(gelu_fast(h[mi][ni][0])));
                unsigned short h1 = __half_as_ushort(__float2half_rn(gelu_fast(h[mi][ni][1])));
                unsigned short h2 = __half_as_ushort(__float2half_rn(gelu_fast(h[mi][ni][2])));
                unsigned short h3 = __half_as_ushort(__float2half_rn(gelu_fast(h[mi][ni][3])));
                *(uint32_t*)(smem + SM_H + r_ * RPITCH + cb) = (uint32_t)h0 | ((uint32_t)h1 << 16);
                *(uint32_t*)(smem + SM_H + (r_ + 8) * RPITCH + cb) = (uint32_t)h2 | ((uint32_t)h3 << 16);
            }
        __syncthreads();
#pragma unroll
        for (int i = 0; i < 8; i++) {
            int idx = tid + i * 256;
            int k = idx >> 4, j = idx & 15;
            *(int4*)(smem + SM_W + k * RPITCH + j * 16) =
                *(const int4*)(w2h + (ch * 128 + k) * 128 + j * 8);
        }
        __syncthreads();
#pragma unroll 2
        for (int ks = 0; ks < 8; ks++) {
            int k0 = ks * 16;
            uint32_t a[2][4], b[8];
#pragma unroll
            for (int mi = 0; mi < 2; mi++)
                ldmx4(a[mi], sb + SM_H + (wm + mi * 16) * RPITCH + k0 * 2 + aoffs);
            ldmx4t(b,     sb + SM_W + k0 * RPITCH + wn * 2 + aoffs);
            ldmx4t(b + 4, sb + SM_W + k0 * RPITCH + (wn + 16) * 2 + aoffs);
#pragma unroll
            for (int mi = 0; mi < 2; mi++)
#pragma unroll
                for (int ni = 0; ni < 4; ni++)
                    mma16816(o[mi][ni], a[mi], b + 2 * ni);
        }
    }

    // ---- epilogue: +xproj, LN(g2), LN(g3), scatter ----
    __syncthreads();
    float* OB = (float*)(smem);                // [64][132]
#pragma unroll
    for (int mi = 0; mi < 2; mi++)
#pragma unroll
        for (int ni = 0; ni < 4; ni++) {
            int r_ = wm + mi * 16 + l4;
            int c_ = wn + ni * 8 + lc;
            *(float2*)(OB + r_ * 132 + c_) = make_float2(o[mi][ni][0], o[mi][ni][1]);
            *(float2*)(OB + (r_ + 8) * 132 + c_) = make_float2(o[mi][ni][2], o[mi][ni][3]);
        }
    __syncthreads();

    const int m = tid & 63, cq = tid >> 6;
    const int c0 = cq * 32;
    float v[32];
    {
        const float* rp = xproj + (R0 + m) * 128 + c0;
#pragma unroll
        for (int g = 0; g < 8; g++) {
            float4 u = *(const float4*)(rp + 4 * g);
            float4 a = *(const float4*)(OB + m * 132 + c0 + 4 * g);
            v[4 * g + 0] = a.x + u.x; v[4 * g + 1] = a.y + u.y;
            v[4 * g + 2] = a.z + u.z; v[4 * g + 3] = a.w + u.w;
        }
    }
    {
        float s = 0.f, q = 0.f;
#pragma unroll
        for (int j = 0; j < 32; j++) { s += v[j]; q += v[j] * v[j]; }
        part[cq * 64 + m] = make_float2(s, q);
    }
    __syncthreads();
    {
        float s = 0.f, q = 0.f;
#pragma unroll
        for (int p_ = 0; p_ < 4; p_++) {
            float2 pp = part[p_ * 64 + m];
            s += pp.x; q += pp.y;
        }
        float mean = s * 0.0078125f;
        float rstd = rsqrtf(fmaxf(q * 0.0078125f - mean * mean, 0.f) + 1e-5f);
#pragma unroll
        for (int j = 0; j < 32; j++)
            v[j] = (v[j] - mean) * rstd * __ldg(&ga[c0 + j]) + __ldg(&ba[c0 + j]);
    }
    __syncthreads();
    {
        float s = 0.f, q = 0.f;
#pragma unroll
        for (int j = 0; j < 32; j++) { s += v[j]; q += v[j] * v[j]; }
        part[cq * 64 + m] = make_float2(s, q);
    }
    __syncthreads();
    float s = 0.f, q = 0.f;
#pragma unroll
    for (int p_ = 0; p_ < 4; p_++) {
        float2 pp = part[p_ * 64 + m];
        s += pp.x; q += pp.y;
    }
    float m2v = s * 0.0078125f;
    float rstd2 = rsqrtf(fmaxf(q * 0.0078125f - m2v * m2v, 0.f) + 1e-5f);
    int t = tb0 + m;
    int ob = (((bI << 10) + t) * 32 + lI) * 128 + c0;
#pragma unroll
    for (int g = 0; g < 8; g++) {
        float4 w;
        w.x = (v[4 * g + 0] - m2v) * rstd2 * __ldg(&gb[c0 + 4 * g + 0]) + __ldg(&bb[c0 + 4 * g + 0]);
        w.y = (v[4 * g + 1] - m2v) * rstd2 * __ldg(&gb[c0 + 4 * g + 1]) + __ldg(&bb[c0 + 4 * g + 1]);
        w.z = (v[4 * g + 2] - m2v) * rstd2 * __ldg(&gb[c0 + 4 * g + 2]) + __ldg(&bb[c0 + 4 * g + 2]);
        w.w = (v[4 * g + 3] - m2v) * rstd2 * __ldg(&gb[c0 + 4 * g + 3]) + __ldg(&bb[c0 + 4 * g + 3]);
        *(float4*)(out + ob + 4 * g) = w;
    }
}

// ============ merged K/V projection (blocks 0..127) + router proj (128..137) ============
#define SMEM_KV (34688 * 4)
__global__ __launch_bounds__(256, 1) void kvr_kernel(
    const float* __restrict__ xp,
    const float* __restrict__ wk, const float* __restrict__ bk,
    const float* __restrict__ wv, const float* __restrict__ bv,
    const float* __restrict__ router, const float* __restrict__ wr, const float* __restrict__ br,
    float* __restrict__ k15, float* __restrict__ v15, float* __restrict__ rp)
{
    extern __shared__ float sm[];
    const int tid = threadIdx.x;
    if (blockIdx.x < 128) {
        float* Xs = sm;
        float* Wks = sm + 1920;
        float* Wvs = sm + 18304;
        const int bl = blockIdx.x;
        for (int idx = tid; idx < 1920; idx += 256)
            Xs[idx] = xp[(bl * 1024 + (idx >> 7)) * 128 + (idx & 127)];
        for (int idx = tid; idx < 16384; idx += 256) { Wks[idx] = wk[idx]; Wvs[idx] = wv[idx]; }
        __syncthreads();
        const int m = tid >> 7, n = tid & 127;
        const float* W = m ? Wvs : Wks;
        const float bsv = m ? __ldg(&bv[n]) : __ldg(&bk[n]);
        float* o = m ? v15 : k15;
        for (int t = 0; t < 15; t++) {
            float acc = bsv;
#pragma unroll 8
            for (int k = 0; k < 128; k++) acc += Xs[t * 128 + k] * W[k * 128 + n];
            o[(bl * 15 + t) * 128 + n] = acc;
        }
    } else {
        float* Ws = sm;
        float* Rs = sm + 16384;
        const int row0 = (blockIdx.x - 128) * 32;
        for (int idx = tid; idx < 16384; idx += 256) Ws[idx] = wr[idx];
        for (int idx = tid; idx < 4096; idx += 256)
            Rs[idx] = router[(row0 + (idx >> 7)) * 128 + (idx & 127)];
        __syncthreads();
        const int n = tid & 127, rbase = (tid >> 7) * 16;
        const float bb_ = __ldg(&br[n]);
        for (int rr = 0; rr < 16; rr++) {
            int r = rbase + rr;
            float acc = bb_;
#pragma unroll 8
            for (int k = 0; k < 128; k++) acc += Rs[r * 128 + k] * Ws[k * 128 + n];
            rp[(row0 + r) * 128 + n] = acc;
        }
    }
}

// ============ merged buffer attention + M2/c2 (block per bl) ============
__global__ __launch_bounds__(256) void buf_m2_kernel(
    const float* __restrict__ rp, const float* __restrict__ k15,
    const float* __restrict__ v15,
    const float* __restrict__ wq, const float* __restrict__ bq,
    float* __restrict__ buf, __half* __restrict__ m2, float* __restrict__ c2)
{
    __shared__ float bufS[1280];
    const int bl = blockIdx.x;
    const int tid = threadIdx.x;
    const int wid = tid >> 5, lane = tid & 31;
    const int l = bl & 31;

    // ---- phase 1: buffer attention, warp per (h,i), 20 pairs over 8 warps ----
    for (int p = wid; p < 20; p += 8) {
        const int h = p / 10, i = p - (p / 10) * 10;
        const float* q = rp + (l * 10 + i) * 128 + h * 64;
        const float q0 = q[lane], q1 = q[lane + 32];
        const int jlo = (i > 5) ? (i - 5) : 0;
        const int cnt = i + 5 - jlo + 1;
        float s[11];
#pragma unroll
        for (int jj = 0; jj < 11; jj++) {
            float d = 0.f;
            if (jj < cnt) {
                int base = (bl * 15 + jlo + jj) * 128 + h * 64;
                d = q0 * k15[base + lane] + q1 * k15[base + lane + 32];
            }
            d += __shfl_xor_sync(0xffffffffu, d, 16);
            d += __shfl_xor_sync(0xffffffffu, d, 8);
            d += __shfl_xor_sync(0xffffffffu, d, 4);
            d += __shfl_xor_sync(0xffffffffu, d, 2);
            d += __shfl_xor_sync(0xffffffffu, d, 1);
            s[jj] = fminf(fmaxf(d * 0.125f, -CLAMPV), CLAMPV);
        }
        float mx = -1e30f;
#pragma unroll
        for (int jj = 0; jj < 11; jj++) if (jj < cnt) mx = fmaxf(mx, s[jj]);
        float den = 0.f, o0 = 0.f, o1 = 0.f;
#pragma unroll
        for (int jj = 0; jj < 11; jj++) {
            if (jj < cnt) {
                float pv = expf(s[jj] - mx);
                den += pv;
                int vbase = (bl * 15 + jlo + jj) * 128 + h * 64;
                o0 += pv * v15[vbase + lane];
                o1 += pv * v15[vbase + lane + 32];
            }
        }
        float rinv = 1.f / den;
        int sbo = (h * 10 + i) * 64;
        bufS[sbo + lane] = o0 * rinv;
        bufS[sbo + lane + 32] = o1 * rinv;
        int ob = ((bl * 2 + h) * 10 + i) * 64;
        buf[ob + lane] = o0 * rinv;
        buf[ob + lane + 32] = o1 * rinv;
    }
    __syncthreads();

    // ---- phase 2: M2 = Wq @ bufS^T (fp16), c2 = bq . bufS ----
    const int n = tid & 31, h = n >> 4, j = n & 15;
    const float* bv = bufS + h * 640 + j * 64;
#pragma unroll 1
    for (int it = 0; it < 16; it++) {
        int k = (tid >> 5) + (it << 3);
        float acc = 0.f;
        if (j < 10) {
            const float* wr = wq + k * 128 + h * 64;
#pragma unroll 8
            for (int d = 0; d < 64; d++) acc += wr[d] * bv[d];
        }
        m2[(bl << 12) + (k << 5) + n] = __float2half_rn(acc);
    }
    if (tid < 32) {
        float c = 0.f;
        if (j < 10) {
            const float* br_ = bq + h * 64;
#pragma unroll 8
            for (int d = 0; d < 64; d++) c += br_[d] * bv[d];
        }
        c2[(bl << 5) + tid] = c;
    }
}

// ============ launch ============
extern "C" void kernel_launch(void* const* d_in, const int* in_sizes, int n_in,
                              void* d_out, int out_size)
{
    const float* x        = (const float*)d_in[0];
    const float* router   = (const float*)d_in[1];
    const float* w_router = (const float*)d_in[2];
    const float* b_router = (const float*)d_in[3];
    const float* w_k      = (const float*)d_in[4];
    const float* b_k      = (const float*)d_in[5];
    const float* w_v      = (const float*)d_in[6];
    const float* b_v      = (const float*)d_in[7];
    const float* w_q      = (const float*)d_in[8];
    const float* b_q      = (const float*)d_in[9];
    const float* m1w1 = (const float*)d_in[10];
    const float* m1b1 = (const float*)d_in[11];
    const float* m1w2 = (const float*)d_in[12];
    const float* m1b2 = (const float*)d_in[13];
    const float* m2w1 = (const float*)d_in[14];
    const float* m2b1 = (const float*)d_in[15];
    const float* m2w2 = (const float*)d_in[16];
    const float* m2b2 = (const float*)d_in[17];
    const float* g1  = (const float*)d_in[18];
    const float* be1 = (const float*)d_in[19];
    const float* g2  = (const float*)d_in[20];
    const float* be2 = (const float*)d_in[21];
    const float* g3  = (const float*)d_in[22];
    const float* be3 = (const float*)d_in[23];
    float* out = (float*)d_out;

    float *xproj, *k15, *v15, *rproj, *bufp, *c2p;
    __half *w16, *m2p;
    cudaGetSymbolAddress((void**)&xproj, g_xproj);
    cudaGetSymbolAddress((void**)&k15,   g_k15);
    cudaGetSymbolAddress((void**)&v15,   g_v15);
    cudaGetSymbolAddress((void**)&rproj, g_rproj);
    cudaGetSymbolAddress((void**)&bufp,  g_buf);
    cudaGetSymbolAddress((void**)&w16,   g_w16);
    cudaGetSymbolAddress((void**)&m2p,   g_m2);
    cudaGetSymbolAddress((void**)&c2p,   g_c2);

    cudaFuncSetAttribute(fused_mlp1, cudaFuncAttributeMaxDynamicSharedMemorySize, SMEM_A);
    cudaFuncSetAttribute(fused_recv_mlp2, cudaFuncAttributeMaxDynamicSharedMemorySize, SMEM_B);
    cudaFuncSetAttribute(kvr_kernel, cudaFuncAttributeMaxDynamicSharedMemorySize, SMEM_KV);

    // 0. weights -> fp16
    cvt_weights<<<1024, 256>>>(m1w1, m1w2, m2w1, m2w2, w16);
    // 1. x_proj = LN(x + mlp1(x))   [64 rows/CTA, occ=2]
    fused_mlp1<<<2048, 256, SMEM_A>>>(
        x, w16, m1b1, w16 + 65536, m1b2, g1, be1, xproj);
    // 2. K/V (t<15) + router projection
    kvr_kernel<<<138, 256, SMEM_KV>>>(
        xproj, w_k, b_k, w_v, b_v, router, w_router, b_router, k15, v15, rproj);
    // 3. buffer attention + M2/c2 (merged, block per bl)
    buf_m2_kernel<<<128, 256>>>(rproj, k15, v15, w_q, b_q, bufp, m2p, c2p);
    // 4. scores + recv + mlp2 + LN2 + LN3 + scatter   [64 rows/CTA, occ=2]
    fused_recv_mlp2<<<2048, 256, SMEM_B>>>(
        bufp, xproj, m2p, c2p, w16 + 131072, m2b1, w16 + 196608, m2b2,
        g2, be2, g3, be3, out);
}

// round 15
// speedup vs baseline: 1.0949x; 1.0020x over previous
#include <cuda_runtime.h>
#include <cuda_fp16.h>
#include <math.h>
#include <stdint.h>

typedef unsigned long long ull;
#define CLAMPV 10000.0f

// ---------------- static scratch ----------------
__device__ float g_xproj[16777216];   // [BL*T,128]
__device__ float g_k15[245760];       // [BL][15][128]
__device__ float g_v15[245760];
__device__ float g_rproj[40960];      // [32*10][128]
__device__ float g_buf[163840];       // [BL][2][10][64]
__device__ __half g_w16[262144];      // m1w1|m1w2|m2w1|m2w2 (fp16)
__device__ __half g_m2[524288];       // [BL][128][32] fp16 (Wq @ buf)
__device__ float g_c2[4096];          // [BL][32]  (bq . buf_j)

// ---------------- helpers ----------------
__device__ __forceinline__ float gelu_fast(float x) {
    float u = 0.7978845608f * x * (1.0f + 0.044715f * x * x);
    float t; asm("tanh.approx.f32 %0, %1;" : "=f"(t) : "f"(u));
    return 0.5f * x * (1.0f + t);
}
__device__ __forceinline__ uint32_t su32(const void* p) {
    uint32_t a;
    asm("{ .reg .u64 t; cvta.to.shared.u64 t, %1; cvt.u32.u64 %0, t; }" : "=r"(a) : "l"(p));
    return a;
}
__device__ __forceinline__ ull pack4h(float4 v) {
    unsigned short a = __half_as_ushort(__float2half_rn(v.x));
    unsigned short b = __half_as_ushort(__float2half_rn(v.y));
    unsigned short c = __half_as_ushort(__float2half_rn(v.z));
    unsigned short d = __half_as_ushort(__float2half_rn(v.w));
    return (ull)a | ((ull)b << 16) | ((ull)c << 32) | ((ull)d << 48);
}

// ---------------- tensor-core primitives ----------------
__device__ __forceinline__ void ldmx4(uint32_t* r, uint32_t addr) {
    asm volatile("ldmatrix.sync.aligned.m8n8.x4.shared.b16 {%0,%1,%2,%3}, [%4];"
        : "=r"(r[0]), "=r"(r[1]), "=r"(r[2]), "=r"(r[3]) : "r"(addr));
}
__device__ __forceinline__ void ldmx4t(uint32_t* r, uint32_t addr) {
    asm volatile("ldmatrix.sync.aligned.m8n8.x4.trans.shared.b16 {%0,%1,%2,%3}, [%4];"
        : "=r"(r[0]), "=r"(r[1]), "=r"(r[2]), "=r"(r[3]) : "r"(addr));
}
__device__ __forceinline__ void mma16816(float* c, const uint32_t* a, const uint32_t* b) {
    asm volatile("mma.sync.aligned.m16n8k16.row.col.f32.f16.f16.f32 "
        "{%0,%1,%2,%3}, {%4,%5,%6,%7}, {%8,%9}, {%0,%1,%2,%3};"
        : "+f"(c[0]), "+f"(c[1]), "+f"(c[2]), "+f"(c[3])
        : "r"(a[0]), "r"(a[1]), "r"(a[2]), "r"(a[3]), "r"(b[0]), "r"(b[1]));
}

// ============ weight pre-conversion ============
__global__ void cvt_weights(const float* __restrict__ w1a, const float* __restrict__ w2a,
                            const float* __restrict__ w1b, const float* __restrict__ w2b,
                            __half* __restrict__ o)
{
    int i = blockIdx.x * 256 + threadIdx.x;
    if (i >= 262144) return;
    float v;
    if (i < 65536) v = w1a[i];
    else if (i < 131072) v = w2a[i - 65536];
    else if (i < 196608) v = w1b[i - 131072];
    else v = w2b[i - 196608];
    o[i] = __float2half_rn(v);
}

// ---------------- shared smem layout (64-row tiles, occ=2) ----------------
#define RPITCH 272
#define SM_X   0        // 64*272 = 17408
#define SM_W   17408    // 128*272 = 34816
#define SM_H   52224    // 64*272 = 17408
#define SM_P   69632    // 4*64 float2 = 2048
#define SMEM_A 71680
#define SM_BUF 71680    // 1280 floats
#define SM_C2  76800    // 32 floats
#define SMEM_B 76928

// ======================================================================
// Kernel A: gather x -> MLP1 (fp16 mma) -> +x -> LN(g1) -> xproj
// 64 rows/CTA, 256 threads, 8 warps (2x4 grid of 32x32 tiles), occ=2
// ======================================================================
__global__ __launch_bounds__(256, 2) void fused_mlp1(
    const float* __restrict__ in,
    const __half* __restrict__ w1h, const float* __restrict__ b1,
    const __half* __restrict__ w2h, const float* __restrict__ b2,
    const float* __restrict__ ga, const float* __restrict__ ba,
    float* __restrict__ xproj)
{
    extern __shared__ char smem[];
    const int tid = threadIdx.x;
    const int wid = tid >> 5;
    const int lane = tid & 31;
    const int R0 = blockIdx.x * 64;
    const int bl0 = R0 >> 10;
    const int bI = bl0 >> 5, lI = bl0 & 31, tb0 = R0 & 1023;
    const uint32_t sb = su32(smem);
    float2* part = (float2*)(smem + SM_P);   // [4][64]

    // ---- stage X fp16 (gathered): 64 rows ----
#pragma unroll
    for (int i = 0; i < 8; i++) {
        int idx = tid + i * 256;
        int m = idx >> 5, k4 = (idx & 31) * 4;
        int grow = (((bI << 10) + tb0 + m) << 5) + lI;
        float4 v = *(const float4*)(in + grow * 128 + k4);
        *(ull*)(smem + SM_X + m * RPITCH + k4 * 2) = pack4h(v);
    }

    const int wm = (wid >> 2) * 32;
    const int wn = (wid & 3) * 32;
    const int l4 = lane >> 2, lc = (lane & 3) * 2;
    const uint32_t aoffs = (uint32_t)((((lane >> 3) & 1) * 8 + (lane & 7)) * RPITCH
                                      + (((lane >> 4) & 1) * 8) * 2);

    float o[2][4][4];
#pragma unroll
    for (int ni = 0; ni < 4; ni++) {
        int col = wn + ni * 8 + lc;
        float bv0 = __ldg(&b2[col]), bv1 = __ldg(&b2[col + 1]);
#pragma unroll
        for (int mi = 0; mi < 2; mi++) {
            o[mi][ni][0] = bv0; o[mi][ni][1] = bv1;
            o[mi][ni][2] = bv0; o[mi][ni][3] = bv1;
        }
    }

    for (int ch = 0; ch < 4; ch++) {
        __syncthreads();
#pragma unroll
        for (int i = 0; i < 8; i++) {
            int idx = tid + i * 256;
            int k = idx >> 4, j = idx & 15;
            *(int4*)(smem + SM_W + k * RPITCH + j * 16) =
                *(const int4*)(w1h + k * 512 + ch * 128 + j * 8);
        }
        __syncthreads();

        float h[2][4][4];
#pragma unroll
        for (int ni = 0; ni < 4; ni++) {
            int col = wn + ni * 8 + lc;
            float bv0 = __ldg(&b1[ch * 128 + col]), bv1 = __ldg(&b1[ch * 128 + col + 1]);
#pragma unroll
            for (int mi = 0; mi < 2; mi++) {
                h[mi][ni][0] = bv0; h[mi][ni][1] = bv1;
                h[mi][ni][2] = bv0; h[mi][ni][3] = bv1;
            }
        }
#pragma unroll 2
        for (int ks = 0; ks < 8; ks++) {
            int k0 = ks * 16;
            uint32_t a[2][4], b[8];
#pragma unroll
            for (int mi = 0; mi < 2; mi++)
                ldmx4(a[mi], sb + SM_X + (wm + mi * 16) * RPITCH + k0 * 2 + aoffs);
            ldmx4t(b,     sb + SM_W + k0 * RPITCH + wn * 2 + aoffs);
            ldmx4t(b + 4, sb + SM_W + k0 * RPITCH + (wn + 16) * 2 + aoffs);
#pragma unroll
            for (int mi = 0; mi < 2; mi++)
#pragma unroll
                for (int ni = 0; ni < 4; ni++)
                    mma16816(h[mi][ni], a[mi], b + 2 * ni);
        }
#pragma unroll
        for (int mi = 0; mi < 2; mi++)
#pragma unroll
            for (int ni = 0; ni < 4; ni++) {
                int r_ = wm + mi * 16 + l4;
                int cb = (wn + ni * 8 + lc) * 2;
                unsigned short h0 = __half_as_ushort(__float2half_rn(gelu_fast(h[mi][ni][0])));
                unsigned short h1 = __half_as_ushort(__float2half_rn(gelu_fast(h[mi][ni][1])));
                unsigned short h2 = __half_as_ushort(__float2half_rn(gelu_fast(h[mi][ni][2])));
                unsigned short h3 = __half_as_ushort(__float2half_rn(gelu_fast(h[mi][ni][3])));
                *(uint32_t*)(smem + SM_H + r_ * RPITCH + cb) = (uint32_t)h0 | ((uint32_t)h1 << 16);
                *(uint32_t*)(smem + SM_H + (r_ + 8) * RPITCH + cb) = (uint32_t)h2 | ((uint32_t)h3 << 16);
            }
        __syncthreads();
#pragma unroll
        for (int i = 0; i < 8; i++) {
            int idx = tid + i * 256;
            int k = idx >> 4, j = idx & 15;
            *(int4*)(smem + SM_W + k * RPITCH + j * 16) =
                *(const int4*)(w2h + (ch * 128 + k) * 128 + j * 8);
        }
        __syncthreads();
#pragma unroll 2
        for (int ks = 0; ks < 8; ks++) {
            int k0 = ks * 16;
            uint32_t a[2][4], b[8];
#pragma unroll
            for (int mi = 0; mi < 2; mi++)
                ldmx4(a[mi], sb + SM_H + (wm + mi * 16) * RPITCH + k0 * 2 + aoffs);
            ldmx4t(b,     sb + SM_W + k0 * RPITCH + wn * 2 + aoffs);
            ldmx4t(b + 4, sb + SM_W + k0 * RPITCH + (wn + 16) * 2 + aoffs);
#pragma unroll
            for (int mi = 0; mi < 2; mi++)
#pragma unroll
                for (int ni = 0; ni < 4; ni++)
                    mma16816(o[mi][ni], a[mi], b + 2 * ni);
        }
    }

    // ---- epilogue: dump -> +x -> LN -> xproj ----
    __syncthreads();
    float* OB = (float*)(smem);                // [64][132]
#pragma unroll
    for (int mi = 0; mi < 2; mi++)
#pragma unroll
        for (int ni = 0; ni < 4; ni++) {
            int r_ = wm + mi * 16 + l4;
            int c_ = wn + ni * 8 + lc;
            *(float2*)(OB + r_ * 132 + c_) = make_float2(o[mi][ni][0], o[mi][ni][1]);
            *(float2*)(OB + (r_ + 8) * 132 + c_) = make_float2(o[mi][ni][2], o[mi][ni][3]);
        }
    __syncthreads();

    const int m = tid & 63, cq = tid >> 6;
    const int c0 = cq * 32;
    float v[32];
    {
        int grow = (((bI << 10) + tb0 + m) << 5) + lI;
        const float* rp = in + grow * 128 + c0;
#pragma unroll
        for (int g = 0; g < 8; g++) {
            float4 u = *(const float4*)(rp + 4 * g);
            float4 a = *(const float4*)(OB + m * 132 + c0 + 4 * g);
            v[4 * g + 0] = a.x + u.x; v[4 * g + 1] = a.y + u.y;
            v[4 * g + 2] = a.z + u.z; v[4 * g + 3] = a.w + u.w;
        }
    }
    {
        float s = 0.f, q = 0.f;
#pragma unroll
        for (int j = 0; j < 32; j++) { s += v[j]; q += v[j] * v[j]; }
        part[cq * 64 + m] = make_float2(s, q);
    }
    __syncthreads();
    {
        float s = 0.f, q = 0.f;
#pragma unroll
        for (int p_ = 0; p_ < 4; p_++) {
            float2 pp = part[p_ * 64 + m];
            s += pp.x; q += pp.y;
        }
        float mean = s * 0.0078125f;
        float rstd = rsqrtf(fmaxf(q * 0.0078125f - mean * mean, 0.f) + 1e-5f);
#pragma unroll
        for (int j = 0; j < 32; j++)
            v[j] = (v[j] - mean) * rstd * __ldg(&ga[c0 + j]) + __ldg(&ba[c0 + j]);
    }
    const int Rg = R0 + m;
#pragma unroll
    for (int g = 0; g < 8; g++)
        *(float4*)(xproj + Rg * 128 + c0 + 4 * g) =
            make_float4(v[4 * g], v[4 * g + 1], v[4 * g + 2], v[4 * g + 3]);
}

// ======================================================================
// Kernel B: scores via M2 (mma) -> softmax/recv -> MLP2 -> +xproj
//           -> LN(g2) -> LN(g3) -> scatter. 64 rows/CTA, occ=2.
// ======================================================================
__global__ __launch_bounds__(256, 2) void fused_recv_mlp2(
    const float* __restrict__ bufp, const float* __restrict__ xproj,
    const __half* __restrict__ m2, const float* __restrict__ c2,
    const __half* __restrict__ w1h, const float* __restrict__ b1,
    const __half* __restrict__ w2h, const float* __restrict__ b2,
    const float* __restrict__ ga, const float* __restrict__ ba,
    const float* __restrict__ gb, const float* __restrict__ bb,
    float* __restrict__ out)
{
    extern __shared__ char smem[];
    const int tid = threadIdx.x;
    const int wid = tid >> 5;
    const int lane = tid & 31;
    const int R0 = blockIdx.x * 64;
    const int bl0 = R0 >> 10;
    const int bI = bl0 >> 5, lI = bl0 & 31, tb0 = R0 & 1023;
    const uint32_t sb = su32(smem);
    float2* part = (float2*)(smem + SM_P);
    float* BUFS = (float*)(smem + SM_BUF);   // [2][10][64]
    float* C2S  = (float*)(smem + SM_C2);    // [32]
    float* SC   = (float*)(smem + SM_H);     // scores [64][36]

    // ---- stage BUFS, M2 tile (SM_W), c2, xproj fp16 (SM_X) ----
    for (int idx = tid; idx < 1280; idx += 256)
        BUFS[idx] = bufp[bl0 * 1280 + idx];
#pragma unroll
    for (int i = 0; i < 2; i++) {
        int idx = tid + i * 256;
        int k = idx >> 2, seg = idx & 3;
        *(int4*)(smem + SM_W + k * RPITCH + seg * 16) =
            *(const int4*)(m2 + (bl0 << 12) + (k << 5) + seg * 8);
    }
    if (tid < 32) C2S[tid] = c2[(bl0 << 5) + tid];
#pragma unroll
    for (int i = 0; i < 8; i++) {
        int idx = tid + i * 256;
        int m_ = idx >> 5, k4 = (idx & 31) * 4;
        float4 v = *(const float4*)(xproj + (R0 + m_) * 128 + k4);
        *(ull*)(smem + SM_X + m_ * RPITCH + k4 * 2) = pack4h(v);
    }
    __syncthreads();

    const int l4 = lane >> 2, lc = (lane & 3) * 2;
    const uint32_t aoffs = (uint32_t)((((lane >> 3) & 1) * 8 + (lane & 7)) * RPITCH
                                      + (((lane >> 4) & 1) * 8) * 2);

    // ---- score mma: rows 0..63 x [k=128] x [n=32]; warps 0..3 ----
    if (wid < 4) {
        const int wm2 = wid * 16;
        float sc[4][4];
#pragma unroll
        for (int ni = 0; ni < 4; ni++) { sc[ni][0] = sc[ni][1] = sc[ni][2] = sc[ni][3] = 0.f; }
#pragma unroll 2
        for (int ks = 0; ks < 8; ks++) {
            int k0 = ks * 16;
            uint32_t a[4], b[8];
            ldmx4(a, sb + SM_X + wm2 * RPITCH + k0 * 2 + aoffs);
            ldmx4t(b,     sb + SM_W + k0 * RPITCH + aoffs);
            ldmx4t(b + 4, sb + SM_W + k0 * RPITCH + 32 + aoffs);
#pragma unroll
            for (int ni = 0; ni < 4; ni++)
                mma16816(sc[ni], a, b + 2 * ni);
        }
#pragma unroll
        for (int ni = 0; ni < 4; ni++) {
            int n = ni * 8 + lc;
            *(float2*)(SC + (wm2 + l4) * 36 + n)     = make_float2(sc[ni][0], sc[ni][1]);
            *(float2*)(SC + (wm2 + l4 + 8) * 36 + n) = make_float2(sc[ni][2], sc[ni][3]);
        }
    }
    __syncthreads();

    // ---- softmax + recv: thread = (r 0..63, hd, half32) ----
    {
        const int r = tid & 63, hd = (tid >> 6) & 1, hf = tid >> 7;
        const int t = tb0 + r;
        float s[10];
#pragma unroll
        for (int j = 0; j < 10; j++) {
            float sv = (SC[r * 36 + hd * 16 + j] + C2S[hd * 16 + j]) * 0.125f;
            s[j] = fminf(fmaxf(sv, -CLAMPV), CLAMPV);
        }
        bool all = (t >= 10);
        float mx = -1e30f;
#pragma unroll
        for (int j = 0; j < 10; j++) {
            bool a = all || (j >= t - 5 && j <= t + 5);
            if (a) mx = fmaxf(mx, s[j]);
        }
        float p[10], den = 0.f;
#pragma unroll
        for (int j = 0; j < 10; j++) {
            bool a = all || (j >= t - 5 && j <= t + 5);
            p[j] = a ? expf(s[j] - mx) : 0.f;
            den += p[j];
        }
        float rinv = 1.f / den;
#pragma unroll
        for (int j = 0; j < 10; j++) p[j] *= rinv;
        const float* BF = BUFS + hd * 640 + hf * 32;
#pragma unroll
        for (int g = 0; g < 8; g++) {
            float4 acc = make_float4(0.f, 0.f, 0.f, 0.f);
#pragma unroll
            for (int j = 0; j < 10; j++) {
                float4 bv = *(const float4*)(BF + j * 64 + 4 * g);
                acc.x += p[j] * bv.x; acc.y += p[j] * bv.y;
                acc.z += p[j] * bv.z; acc.w += p[j] * bv.w;
            }
            *(ull*)(smem + SM_X + r * RPITCH + (hd * 64 + hf * 32 + 4 * g) * 2) = pack4h(acc);
        }
    }

    const int wm = (wid >> 2) * 32;
    const int wn = (wid & 3) * 32;

    float o[2][4][4];
#pragma unroll
    for (int ni = 0; ni < 4; ni++) {
        int col = wn + ni * 8 + lc;
        float bv0 = __ldg(&b2[col]), bv1 = __ldg(&b2[col + 1]);
#pragma unroll
        for (int mi = 0; mi < 2; mi++) {
            o[mi][ni][0] = bv0; o[mi][ni][1] = bv1;
            o[mi][ni][2] = bv0; o[mi][ni][3] = bv1;
        }
    }

    for (int ch = 0; ch < 4; ch++) {
        __syncthreads();
#pragma unroll
        for (int i = 0; i < 8; i++) {
            int idx = tid + i * 256;
            int k = idx >> 4, j = idx & 15;
            *(int4*)(smem + SM_W + k * RPITCH + j * 16) =
                *(const int4*)(w1h + k * 512 + ch * 128 + j * 8);
        }
        __syncthreads();

        float h[2][4][4];
#pragma unroll
        for (int ni = 0; ni < 4; ni++) {
            int col = wn + ni * 8 + lc;
            float bv0 = __ldg(&b1[ch * 128 + col]), bv1 = __ldg(&b1[ch * 128 + col + 1]);
#pragma unroll
            for (int mi = 0; mi < 2; mi++) {
                h[mi][ni][0] = bv0; h[mi][ni][1] = bv1;
                h[mi][ni][2] = bv0; h[mi][ni][3] = bv1;
            }
        }
#pragma unroll 2
        for (int ks = 0; ks < 8; ks++) {
            int k0 = ks * 16;
            uint32_t a[2][4], b[8];
#pragma unroll
            for (int mi = 0; mi < 2; mi++)
                ldmx4(a[mi], sb + SM_X + (wm + mi * 16) * RPITCH + k0 * 2 + aoffs);
            ldmx4t(b,     sb + SM_W + k0 * RPITCH + wn * 2 + aoffs);
            ldmx4t(b + 4, sb + SM_W + k0 * RPITCH + (wn + 16) * 2 + aoffs);
#pragma unroll
            for (int mi = 0; mi < 2; mi++)
#pragma unroll
                for (int ni = 0; ni < 4; ni++)
                    mma16816(h[mi][ni], a[mi], b + 2 * ni);
        }
#pragma unroll
        for (int mi = 0; mi < 2; mi++)
#pragma unroll
            for (int ni = 0; ni < 4; ni++) {
                int r_ = wm + mi * 16 + l4;
                int cb = (wn + ni * 8 + lc) * 2;
                unsigned short h0 = __half_as_ushort(__float2half_rn(gelu_fast(h[mi][ni][0])));
                unsigned short h1 = __half_as_ushort(__float2half_rn(gelu_fast(h[mi][ni][1])));
                unsigned short h2 = __half_as_ushort(__float2half_rn(gelu_fast(h[mi][ni][2])));
                unsigned short h3 = __half_as_ushort(__float2half_rn(gelu_fast(h[mi][ni][3])));
                *(uint32_t*)(smem + SM_H + r_ * RPITCH + cb) = (uint32_t)h0 | ((uint32_t)h1 << 16);
                *(uint32_t*)(smem + SM_H + (r_ + 8) * RPITCH + cb) = (uint32_t)h2 | ((uint32_t)h3 << 16);
            }
        __syncthreads();
#pragma unroll
        for (int i = 0; i < 8; i++) {
            int idx = tid + i * 256;
            int k = idx >> 4, j = idx & 15;
            *(int4*)(smem + SM_W + k * RPITCH + j * 16) =
                *(const int4*)(w2h + (ch * 128 + k) * 128 + j * 8);
        }
        __syncthreads();
#pragma unroll 2
        for (int ks = 0; ks < 8; ks++) {
            int k0 = ks * 16;
            uint32_t a[2][4], b[8];
#pragma unroll
            for (int mi = 0; mi < 2; mi++)
                ldmx4(a[mi], sb + SM_H + (wm + mi * 16) * RPITCH + k0 * 2 + aoffs);
            ldmx4t(b,     sb + SM_W + k0 * RPITCH + wn * 2 + aoffs);
            ldmx4t(b + 4, sb + SM_W + k0 * RPITCH + (wn + 16) * 2 + aoffs);
#pragma unroll
            for (int mi = 0; mi < 2; mi++)
#pragma unroll
                for (int ni = 0; ni < 4; ni++)
                    mma16816(o[mi][ni], a[mi], b + 2 * ni);
        }
    }

    // ---- epilogue: +xproj, LN(g2), LN(g3), scatter ----
    __syncthreads();
    float* OB = (float*)(smem);                // [64][132]
#pragma unroll
    for (int mi = 0; mi < 2; mi++)
#pragma unroll
        for (int ni = 0; ni < 4; ni++) {
            int r_ = wm + mi * 16 + l4;
            int c_ = wn + ni * 8 + lc;
            *(float2*)(OB + r_ * 132 + c_) = make_float2(o[mi][ni][0], o[mi][ni][1]);
            *(float2*)(OB + (r_ + 8) * 132 + c_) = make_float2(o[mi][ni][2], o[mi][ni][3]);
        }
    __syncthreads();

    const int m = tid & 63, cq = tid >> 6;
    const int c0 = cq * 32;
    float v[32];
    {
        const float* rp = xproj + (R0 + m) * 128 + c0;
#pragma unroll
        for (int g = 0; g < 8; g++) {
            float4 u = *(const float4*)(rp + 4 * g);
            float4 a = *(const float4*)(OB + m * 132 + c0 + 4 * g);
            v[4 * g + 0] = a.x + u.x; v[4 * g + 1] = a.y + u.y;
            v[4 * g + 2] = a.z + u.z; v[4 * g + 3] = a.w + u.w;
        }
    }
    {
        float s = 0.f, q = 0.f;
#pragma unroll
        for (int j = 0; j < 32; j++) { s += v[j]; q += v[j] * v[j]; }
        part[cq * 64 + m] = make_float2(s, q);
    }
    __syncthreads();
    {
        float s = 0.f, q = 0.f;
#pragma unroll
        for (int p_ = 0; p_ < 4; p_++) {
            float2 pp = part[p_ * 64 + m];
            s += pp.x; q += pp.y;
        }
        float mean = s * 0.0078125f;
        float rstd = rsqrtf(fmaxf(q * 0.0078125f - mean * mean, 0.f) + 1e-5f);
#pragma unroll
        for (int j = 0; j < 32; j++)
            v[j] = (v[j] - mean) * rstd * __ldg(&ga[c0 + j]) + __ldg(&ba[c0 + j]);
    }
    __syncthreads();
    {
        float s = 0.f, q = 0.f;
#pragma unroll
        for (int j = 0; j < 32; j++) { s += v[j]; q += v[j] * v[j]; }
        part[cq * 64 + m] = make_float2(s, q);
    }
    __syncthreads();
    float s = 0.f, q = 0.f;
#pragma unroll
    for (int p_ = 0; p_ < 4; p_++) {
        float2 pp = part[p_ * 64 + m];
        s += pp.x; q += pp.y;
    }
    float m2v = s * 0.0078125f;
    float rstd2 = rsqrtf(fmaxf(q * 0.0078125f - m2v * m2v, 0.f) + 1e-5f);
    int t = tb0 + m;
    int ob = (((bI << 10) + t) * 32 + lI) * 128 + c0;
#pragma unroll
    for (int g = 0; g < 8; g++) {
        float4 w;
        w.x = (v[4 * g + 0] - m2v) * rstd2 * __ldg(&gb[c0 + 4 * g + 0]) + __ldg(&bb[c0 + 4 * g + 0]);
        w.y = (v[4 * g + 1] - m2v) * rstd2 * __ldg(&gb[c0 + 4 * g + 1]) + __ldg(&bb[c0 + 4 * g + 1]);
        w.z = (v[4 * g + 2] - m2v) * rstd2 * __ldg(&gb[c0 + 4 * g + 2]) + __ldg(&bb[c0 + 4 * g + 2]);
        w.w = (v[4 * g + 3] - m2v) * rstd2 * __ldg(&gb[c0 + 4 * g + 3]) + __ldg(&bb[c0 + 4 * g + 3]);
        *(float4*)(out + ob + 4 * g) = w;
    }
}

// ============ merged K/V projection (blocks 0..127) + router proj (128..137) ============
#define SMEM_KV (34688 * 4)
__global__ __launch_bounds__(256, 1) void kvr_kernel(
    const float* __restrict__ xp,
    const float* __restrict__ wk, const float* __restrict__ bk,
    const float* __restrict__ wv, const float* __restrict__ bv,
    const float* __restrict__ router, const float* __restrict__ wr, const float* __restrict__ br,
    float* __restrict__ k15, float* __restrict__ v15, float* __restrict__ rp)
{
    extern __shared__ float sm[];
    const int tid = threadIdx.x;
    if (blockIdx.x < 128) {
        float* Xs = sm;
        float* Wks = sm + 1920;
        float* Wvs = sm + 18304;
        const int bl = blockIdx.x;
        for (int idx = tid; idx < 1920; idx += 256)
            Xs[idx] = xp[(bl * 1024 + (idx >> 7)) * 128 + (idx & 127)];
        for (int idx = tid; idx < 16384; idx += 256) { Wks[idx] = wk[idx]; Wvs[idx] = wv[idx]; }
        __syncthreads();
        const int m = tid >> 7, n = tid & 127;
        const float* W = m ? Wvs : Wks;
        const float bsv = m ? __ldg(&bv[n]) : __ldg(&bk[n]);
        float* o = m ? v15 : k15;
        for (int t = 0; t < 15; t++) {
            float acc = bsv;
#pragma unroll 8
            for (int k = 0; k < 128; k++) acc += Xs[t * 128 + k] * W[k * 128 + n];
            o[(bl * 15 + t) * 128 + n] = acc;
        }
    } else {
        float* Ws = sm;
        float* Rs = sm + 16384;
        const int row0 = (blockIdx.x - 128) * 32;
        for (int idx = tid; idx < 16384; idx += 256) Ws[idx] = wr[idx];
        for (int idx = tid; idx < 4096; idx += 256)
            Rs[idx] = router[(row0 + (idx >> 7)) * 128 + (idx & 127)];
        __syncthreads();
        const int n = tid & 127, rbase = (tid >> 7) * 16;
        const float bb_ = __ldg(&br[n]);
        for (int rr = 0; rr < 16; rr++) {
            int r = rbase + rr;
            float acc = bb_;
#pragma unroll 8
            for (int k = 0; k < 128; k++) acc += Rs[r * 128 + k] * Ws[k * 128 + n];
            rp[(row0 + r) * 128 + n] = acc;
        }
    }
}

// ============ merged buffer attention + M2/c2 (block per bl) ============
__global__ __launch_bounds__(256) void buf_m2_kernel(
    const float* __restrict__ rp, const float* __restrict__ k15,
    const float* __restrict__ v15,
    const float* __restrict__ wq, const float* __restrict__ bq,
    float* __restrict__ buf, __half* __restrict__ m2, float* __restrict__ c2)
{
    __shared__ float bufS[1280];
    const int bl = blockIdx.x;
    const int tid = threadIdx.x;
    const int wid = tid >> 5, lane = tid & 31;
    const int l = bl & 31;

    // ---- phase 1: buffer attention, warp per (h,i), 20 pairs over 8 warps ----
    for (int p = wid; p < 20; p += 8) {
        const int h = p / 10, i = p - (p / 10) * 10;
        const float* q = rp + (l * 10 + i) * 128 + h * 64;
        const float q0 = q[lane], q1 = q[lane + 32];
        const int jlo = (i > 5) ? (i - 5) : 0;
        const int cnt = i + 5 - jlo + 1;
        float s[11];
#pragma unroll
        for (int jj = 0; jj < 11; jj++) {
            float d = 0.f;
            if (jj < cnt) {
                int base = (bl * 15 + jlo + jj) * 128 + h * 64;
                d = q0 * k15[base + lane] + q1 * k15[base + lane + 32];
            }
            d += __shfl_xor_sync(0xffffffffu, d, 16);
            d += __shfl_xor_sync(0xffffffffu, d, 8);
            d += __shfl_xor_sync(0xffffffffu, d, 4);
            d += __shfl_xor_sync(0xffffffffu, d, 2);
            d += __shfl_xor_sync(0xffffffffu, d, 1);
            s[jj] = fminf(fmaxf(d * 0.125f, -CLAMPV), CLAMPV);
        }
        float mx = -1e30f;
#pragma unroll
        for (int jj = 0; jj < 11; jj++) if (jj < cnt) mx = fmaxf(mx, s[jj]);
        float den = 0.f, o0 = 0.f, o1 = 0.f;
#pragma unroll
        for (int jj = 0; jj < 11; jj++) {
            if (jj < cnt) {
                float pv = expf(s[jj] - mx);
                den += pv;
                int vbase = (bl * 15 + jlo + jj) * 128 + h * 64;
                o0 += pv * v15[vbase + lane];
                o1 += pv * v15[vbase + lane + 32];
            }
        }
        float rinv = 1.f / den;
        int sbo = (h * 10 + i) * 64;
        bufS[sbo + lane] = o0 * rinv;
        bufS[sbo + lane + 32] = o1 * rinv;
        int ob = ((bl * 2 + h) * 10 + i) * 64;
        buf[ob + lane] = o0 * rinv;
        buf[ob + lane + 32] = o1 * rinv;
    }
    __syncthreads();

    // ---- phase 2: M2 = Wq @ bufS^T (fp16), c2 = bq . bufS ----
    // lane-rotated reduction order: lane n starts at d = n -> bank (d+n)%32,
    // all 32 lanes hit distinct banks every iteration (was 32-way conflict).
    const int n = tid & 31, h = n >> 4, j = n & 15;
    const float* bv = bufS + h * 640 + j * 64;
#pragma unroll 1
    for (int it = 0; it < 16; it++) {
        int k = (tid >> 5) + (it << 3);
        float acc = 0.f;
        if (j < 10) {
            const float* wr = wq + k * 128 + h * 64;
#pragma unroll
            for (int dd = 0; dd < 64; dd++) {
                int d = (dd + n) & 63;
                acc += wr[d] * bv[d];
            }
        }
        m2[(bl << 12) + (k << 5) + n] = __float2half_rn(acc);
    }
    if (tid < 32) {
        float c = 0.f;
        if (j < 10) {
            const float* br_ = bq + h * 64;
#pragma unroll
            for (int dd = 0; dd < 64; dd++) {
                int d = (dd + n) & 63;
                c += br_[d] * bv[d];
            }
        }
        c2[(bl << 5) + tid] = c;
    }
}

// ============ launch ============
extern "C" void kernel_launch(void* const* d_in, const int* in_sizes, int n_in,
                              void* d_out, int out_size)
{
    const float* x        = (const float*)d_in[0];
    const float* router   = (const float*)d_in[1];
    const float* w_router = (const float*)d_in[2];
    const float* b_router = (const float*)d_in[3];
    const float* w_k      = (const float*)d_in[4];
    const float* b_k      = (const float*)d_in[5];
    const float* w_v      = (const float*)d_in[6];
    const float* b_v      = (const float*)d_in[7];
    const float* w_q      = (const float*)d_in[8];
    const float* b_q      = (const float*)d_in[9];
    const float* m1w1 = (const float*)d_in[10];
    const float* m1b1 = (const float*)d_in[11];
    const float* m1w2 = (const float*)d_in[12];
    const float* m1b2 = (const float*)d_in[13];
    const float* m2w1 = (const float*)d_in[14];
    const float* m2b1 = (const float*)d_in[15];
    const float* m2w2 = (const float*)d_in[16];
    const float* m2b2 = (const float*)d_in[17];
    const float* g1  = (const float*)d_in[18];
    const float* be1 = (const float*)d_in[19];
    const float* g2  = (const float*)d_in[20];
    const float* be2 = (const float*)d_in[21];
    const float* g3  = (const float*)d_in[22];
    const float* be3 = (const float*)d_in[23];
    float* out = (float*)d_out;

    float *xproj, *k15, *v15, *rproj, *bufp, *c2p;
    __half *w16, *m2p;
    cudaGetSymbolAddress((void**)&xproj, g_xproj);
    cudaGetSymbolAddress((void**)&k15,   g_k15);
    cudaGetSymbolAddress((void**)&v15,   g_v15);
    cudaGetSymbolAddress((void**)&rproj, g_rproj);
    cudaGetSymbolAddress((void**)&bufp,  g_buf);
    cudaGetSymbolAddress((void**)&w16,   g_w16);
    cudaGetSymbolAddress((void**)&m2p,   g_m2);
    cudaGetSymbolAddress((void**)&c2p,   g_c2);

    cudaFuncSetAttribute(fused_mlp1, cudaFuncAttributeMaxDynamicSharedMemorySize, SMEM_A);
    cudaFuncSetAttribute(fused_recv_mlp2, cudaFuncAttributeMaxDynamicSharedMemorySize, SMEM_B);
    cudaFuncSetAttribute(kvr_kernel, cudaFuncAttributeMaxDynamicSharedMemorySize, SMEM_KV);

    // 0. weights -> fp16
    cvt_weights<<<1024, 256>>>(m1w1, m1w2, m2w1, m2w2, w16);
    // 1. x_proj = LN(x + mlp1(x))   [64 rows/CTA, occ=2]
    fused_mlp1<<<2048, 256, SMEM_A>>>(
        x, w16, m1b1, w16 + 65536, m1b2, g1, be1, xproj);
    // 2. K/V (t<15) + router projection
    kvr_kernel<<<138, 256, SMEM_KV>>>(
        xproj, w_k, b_k, w_v, b_v, router, w_router, b_router, k15, v15, rproj);
    // 3. buffer attention + M2/c2 (merged, block per bl, conflict-free m2)
    buf_m2_kernel<<<128, 256>>>(rproj, k15, v15, w_q, b_q, bufp, m2p, c2p);
    // 4. scores + recv + mlp2 + LN2 + LN3 + scatter   [64 rows/CTA, occ=2]
    fused_recv_mlp2<<<2048, 256, SMEM_B>>>(
        bufp, xproj, m2p, c2p, w16 + 131072, m2b1, w16 + 196608, m2b2,
        g2, be2, g3, be3, out);
}

// round 16
// speedup vs baseline: 1.1483x; 1.0487x over previous
#include <cuda_runtime.h>
#include <cuda_fp16.h>
#include <math.h>
#include <stdint.h>

typedef unsigned long long ull;
#define CLAMPV 10000.0f

// ---------------- static scratch ----------------
__device__ float g_xproj[16777216];   // [BL*T,128]
__device__ float g_k15[245760];       // [BL][15][128]
__device__ float g_v15[245760];
__device__ float g_rproj[40960];      // [32*10][128]
__device__ float g_buf[163840];       // [BL][2][10][64]
__device__ __half g_w16[262144];      // m1w1|m1w2|m2w1|m2w2 (fp16)
__device__ __half g_m2[524288];       // [BL][128][32] fp16 (Wq @ buf)
__device__ float g_c2[4096];          // [BL][32]  (bq . buf_j)

// ---------------- helpers ----------------
__device__ __forceinline__ float gelu_fast(float x) {
    float u = 0.7978845608f * x * (1.0f + 0.044715f * x * x);
    float t; asm("tanh.approx.f32 %0, %1;" : "=f"(t) : "f"(u));
    return 0.5f * x * (1.0f + t);
}
__device__ __forceinline__ uint32_t su32(const void* p) {
    uint32_t a;
    asm("{ .reg .u64 t; cvta.to.shared.u64 t, %1; cvt.u32.u64 %0, t; }" : "=r"(a) : "l"(p));
    return a;
}
__device__ __forceinline__ ull pack4h(float4 v) {
    unsigned short a = __half_as_ushort(__float2half_rn(v.x));
    unsigned short b = __half_as_ushort(__float2half_rn(v.y));
    unsigned short c = __half_as_ushort(__float2half_rn(v.z));
    unsigned short d = __half_as_ushort(__float2half_rn(v.w));
    return (ull)a | ((ull)b << 16) | ((ull)c << 32) | ((ull)d << 48);
}

// ---------------- tensor-core primitives ----------------
__device__ __forceinline__ void ldmx4(uint32_t* r, uint32_t addr) {
    asm volatile("ldmatrix.sync.aligned.m8n8.x4.shared.b16 {%0,%1,%2,%3}, [%4];"
        : "=r"(r[0]), "=r"(r[1]), "=r"(r[2]), "=r"(r[3]) : "r"(addr));
}
__device__ __forceinline__ void ldmx4t(uint32_t* r, uint32_t addr) {
    asm volatile("ldmatrix.sync.aligned.m8n8.x4.trans.shared.b16 {%0,%1,%2,%3}, [%4];"
        : "=r"(r[0]), "=r"(r[1]), "=r"(r[2]), "=r"(r[3]) : "r"(addr));
}
__device__ __forceinline__ void mma16816(float* c, const uint32_t* a, const uint32_t* b) {
    asm volatile("mma.sync.aligned.m16n8k16.row.col.f32.f16.f16.f32 "
        "{%0,%1,%2,%3}, {%4,%5,%6,%7}, {%8,%9}, {%0,%1,%2,%3};"
        : "+f"(c[0]), "+f"(c[1]), "+f"(c[2]), "+f"(c[3])
        : "r"(a[0]), "r"(a[1]), "r"(a[2]), "r"(a[3]), "r"(b[0]), "r"(b[1]));
}

// ============ weight pre-conversion ============
__global__ void cvt_weights(const float* __restrict__ w1a, const float* __restrict__ w2a,
                            const float* __restrict__ w1b, const float* __restrict__ w2b,
                            __half* __restrict__ o)
{
    int i = blockIdx.x * 256 + threadIdx.x;
    if (i >= 262144) return;
    float v;
    if (i < 65536) v = w1a[i];
    else if (i < 131072) v = w2a[i - 65536];
    else if (i < 196608) v = w1b[i - 131072];
    else v = w2b[i - 196608];
    o[i] = __float2half_rn(v);
}

// ---------------- shared smem layout (64-row tiles, occ=2) ----------------
#define RPITCH 272
#define SM_X   0        // 64*272 = 17408
#define SM_W   17408    // 128*272 = 34816
#define SM_H   52224    // 64*272 = 17408
#define SM_P   69632    // 4*64 float2 = 2048
#define SMEM_A 71680
#define SM_BUF 71680    // 1280 floats
#define SM_C2  76800    // 32 floats
#define SMEM_B 76928

// ======================================================================
// Kernel A: gather x -> MLP1 (fp16 mma) -> +x -> LN(g1) -> xproj
// 64 rows/CTA, 256 threads, 8 warps (2x4 grid of 32x32 tiles), occ=2
// ======================================================================
__global__ __launch_bounds__(256, 2) void fused_mlp1(
    const float* __restrict__ in,
    const __half* __restrict__ w1h, const float* __restrict__ b1,
    const __half* __restrict__ w2h, const float* __restrict__ b2,
    const float* __restrict__ ga, const float* __restrict__ ba,
    float* __restrict__ xproj)
{
    extern __shared__ char smem[];
    const int tid = threadIdx.x;
    const int wid = tid >> 5;
    const int lane = tid & 31;
    const int R0 = blockIdx.x * 64;
    const int bl0 = R0 >> 10;
    const int bI = bl0 >> 5, lI = bl0 & 31, tb0 = R0 & 1023;
    const uint32_t sb = su32(smem);
    float2* part = (float2*)(smem + SM_P);   // [4][64]

    // ---- stage X fp16 (gathered): 64 rows ----
#pragma unroll
    for (int i = 0; i < 8; i++) {
        int idx = tid + i * 256;
        int m = idx >> 5, k4 = (idx & 31) * 4;
        int grow = (((bI << 10) + tb0 + m) << 5) + lI;
        float4 v = *(const float4*)(in + grow * 128 + k4);
        *(ull*)(smem + SM_X + m * RPITCH + k4 * 2) = pack4h(v);
    }

    const int wm = (wid >> 2) * 32;
    const int wn = (wid & 3) * 32;
    const int l4 = lane >> 2, lc = (lane & 3) * 2;
    const uint32_t aoffs = (uint32_t)((((lane >> 3) & 1) * 8 + (lane & 7)) * RPITCH
                                      + (((lane >> 4) & 1) * 8) * 2);

    float o[2][4][4];
#pragma unroll
    for (int ni = 0; ni < 4; ni++) {
        int col = wn + ni * 8 + lc;
        float bv0 = __ldg(&b2[col]), bv1 = __ldg(&b2[col + 1]);
#pragma unroll
        for (int mi = 0; mi < 2; mi++) {
            o[mi][ni][0] = bv0; o[mi][ni][1] = bv1;
            o[mi][ni][2] = bv0; o[mi][ni][3] = bv1;
        }
    }

    for (int ch = 0; ch < 4; ch++) {
        __syncthreads();
#pragma unroll
        for (int i = 0; i < 8; i++) {
            int idx = tid + i * 256;
            int k = idx >> 4, j = idx & 15;
            *(int4*)(smem + SM_W + k * RPITCH + j * 16) =
                *(const int4*)(w1h + k * 512 + ch * 128 + j * 8);
        }
        __syncthreads();

        float h[2][4][4];
#pragma unroll
        for (int ni = 0; ni < 4; ni++) {
            int col = wn + ni * 8 + lc;
            float bv0 = __ldg(&b1[ch * 128 + col]), bv1 = __ldg(&b1[ch * 128 + col + 1]);
#pragma unroll
            for (int mi = 0; mi < 2; mi++) {
                h[mi][ni][0] = bv0; h[mi][ni][1] = bv1;
                h[mi][ni][2] = bv0; h[mi][ni][3] = bv1;
            }
        }
#pragma unroll 2
        for (int ks = 0; ks < 8; ks++) {
            int k0 = ks * 16;
            uint32_t a[2][4], b[8];
#pragma unroll
            for (int mi = 0; mi < 2; mi++)
                ldmx4(a[mi], sb + SM_X + (wm + mi * 16) * RPITCH + k0 * 2 + aoffs);
            ldmx4t(b,     sb + SM_W + k0 * RPITCH + wn * 2 + aoffs);
            ldmx4t(b + 4, sb + SM_W + k0 * RPITCH + (wn + 16) * 2 + aoffs);
#pragma unroll
            for (int mi = 0; mi < 2; mi++)
#pragma unroll
                for (int ni = 0; ni < 4; ni++)
                    mma16816(h[mi][ni], a[mi], b + 2 * ni);
        }
#pragma unroll
        for (int mi = 0; mi < 2; mi++)
#pragma unroll
            for (int ni = 0; ni < 4; ni++) {
                int r_ = wm + mi * 16 + l4;
                int cb = (wn + ni * 8 + lc) * 2;
                unsigned short h0 = __half_as_ushort(__float2half_rn(gelu_fast(h[mi][ni][0])));
                unsigned short h1 = __half_as_ushort(__float2half_rn(gelu_fast(h[mi][ni][1])));
                unsigned short h2 = __half_as_ushort(__float2half_rn(gelu_fast(h[mi][ni][2])));
                unsigned short h3 = __half_as_ushort(__float2half_rn(gelu_fast(h[mi][ni][3])));
                *(uint32_t*)(smem + SM_H + r_ * RPITCH + cb) = (uint32_t)h0 | ((uint32_t)h1 << 16);
                *(uint32_t*)(smem + SM_H + (r_ + 8) * RPITCH + cb) = (uint32_t)h2 | ((uint32_t)h3 << 16);
            }
        __syncthreads();
#pragma unroll
        for (int i = 0; i < 8; i++) {
            int idx = tid + i * 256;
            int k = idx >> 4, j = idx & 15;
            *(int4*)(smem + SM_W + k * RPITCH + j * 16) =
                *(const int4*)(w2h + (ch * 128 + k) * 128 + j * 8);
        }
        __syncthreads();
#pragma unroll 2
        for (int ks = 0; ks < 8; ks++) {
            int k0 = ks * 16;
            uint32_t a[2][4], b[8];
#pragma unroll
            for (int mi = 0; mi < 2; mi++)
                ldmx4(a[mi], sb + SM_H + (wm + mi * 16) * RPITCH + k0 * 2 + aoffs);
            ldmx4t(b,     sb + SM_W + k0 * RPITCH + wn * 2 + aoffs);
            ldmx4t(b + 4, sb + SM_W + k0 * RPITCH + (wn + 16) * 2 + aoffs);
#pragma unroll
            for (int mi = 0; mi < 2; mi++)
#pragma unroll
                for (int ni = 0; ni < 4; ni++)
                    mma16816(o[mi][ni], a[mi], b + 2 * ni);
        }
    }

    // ---- epilogue: dump -> +x -> LN -> xproj ----
    __syncthreads();
    float* OB = (float*)(smem);                // [64][132]
#pragma unroll
    for (int mi = 0; mi < 2; mi++)
#pragma unroll
        for (int ni = 0; ni < 4; ni++) {
            int r_ = wm + mi * 16 + l4;
            int c_ = wn + ni * 8 + lc;
            *(float2*)(OB + r_ * 132 + c_) = make_float2(o[mi][ni][0], o[mi][ni][1]);
            *(float2*)(OB + (r_ + 8) * 132 + c_) = make_float2(o[mi][ni][2], o[mi][ni][3]);
        }
    __syncthreads();

    const int m = tid & 63, cq = tid >> 6;
    const int c0 = cq * 32;
    float v[32];
    {
        int grow = (((bI << 10) + tb0 + m) << 5) + lI;
        const float* rp = in + grow * 128 + c0;
#pragma unroll
        for (int g = 0; g < 8; g++) {
            float4 u = *(const float4*)(rp + 4 * g);
            float4 a = *(const float4*)(OB + m * 132 + c0 + 4 * g);
            v[4 * g + 0] = a.x + u.x; v[4 * g + 1] = a.y + u.y;
            v[4 * g + 2] = a.z + u.z; v[4 * g + 3] = a.w + u.w;
        }
    }
    {
        float s = 0.f, q = 0.f;
#pragma unroll
        for (int j = 0; j < 32; j++) { s += v[j]; q += v[j] * v[j]; }
        part[cq * 64 + m] = make_float2(s, q);
    }
    __syncthreads();
    {
        float s = 0.f, q = 0.f;
#pragma unroll
        for (int p_ = 0; p_ < 4; p_++) {
            float2 pp = part[p_ * 64 + m];
            s += pp.x; q += pp.y;
        }
        float mean = s * 0.0078125f;
        float rstd = rsqrtf(fmaxf(q * 0.0078125f - mean * mean, 0.f) + 1e-5f);
#pragma unroll
        for (int j = 0; j < 32; j++)
            v[j] = (v[j] - mean) * rstd * __ldg(&ga[c0 + j]) + __ldg(&ba[c0 + j]);
    }
    const int Rg = R0 + m;
#pragma unroll
    for (int g = 0; g < 8; g++)
        *(float4*)(xproj + Rg * 128 + c0 + 4 * g) =
            make_float4(v[4 * g], v[4 * g + 1], v[4 * g + 2], v[4 * g + 3]);
}

// ======================================================================
// Kernel B: scores via M2 (mma) -> softmax/recv -> MLP2 -> +xproj
//           -> LN(g2) -> LN(g3) -> scatter. 64 rows/CTA, occ=2.
// ======================================================================
__global__ __launch_bounds__(256, 2) void fused_recv_mlp2(
    const float* __restrict__ bufp, const float* __restrict__ xproj,
    const __half* __restrict__ m2, const float* __restrict__ c2,
    const __half* __restrict__ w1h, const float* __restrict__ b1,
    const __half* __restrict__ w2h, const float* __restrict__ b2,
    const float* __restrict__ ga, const float* __restrict__ ba,
    const float* __restrict__ gb, const float* __restrict__ bb,
    float* __restrict__ out)
{
    extern __shared__ char smem[];
    const int tid = threadIdx.x;
    const int wid = tid >> 5;
    const int lane = tid & 31;
    const int R0 = blockIdx.x * 64;
    const int bl0 = R0 >> 10;
    const int bI = bl0 >> 5, lI = bl0 & 31, tb0 = R0 & 1023;
    const uint32_t sb = su32(smem);
    float2* part = (float2*)(smem + SM_P);
    float* BUFS = (float*)(smem + SM_BUF);   // [2][10][64]
    float* C2S  = (float*)(smem + SM_C2);    // [32]
    float* SC   = (float*)(smem + SM_H);     // scores [64][36]

    // ---- stage BUFS, M2 tile (SM_W), c2, xproj fp16 (SM_X) ----
    for (int idx = tid; idx < 1280; idx += 256)
        BUFS[idx] = bufp[bl0 * 1280 + idx];
#pragma unroll
    for (int i = 0; i < 2; i++) {
        int idx = tid + i * 256;
        int k = idx >> 2, seg = idx & 3;
        *(int4*)(smem + SM_W + k * RPITCH + seg * 16) =
            *(const int4*)(m2 + (bl0 << 12) + (k << 5) + seg * 8);
    }
    if (tid < 32) C2S[tid] = c2[(bl0 << 5) + tid];
#pragma unroll
    for (int i = 0; i < 8; i++) {
        int idx = tid + i * 256;
        int m_ = idx >> 5, k4 = (idx & 31) * 4;
        float4 v = *(const float4*)(xproj + (R0 + m_) * 128 + k4);
        *(ull*)(smem + SM_X + m_ * RPITCH + k4 * 2) = pack4h(v);
    }
    __syncthreads();

    const int l4 = lane >> 2, lc = (lane & 3) * 2;
    const uint32_t aoffs = (uint32_t)((((lane >> 3) & 1) * 8 + (lane & 7)) * RPITCH
                                      + (((lane >> 4) & 1) * 8) * 2);

    // ---- score mma: rows 0..63 x [k=128] x [n=32]; warps 0..3 ----
    if (wid < 4) {
        const int wm2 = wid * 16;
        float sc[4][4];
#pragma unroll
        for (int ni = 0; ni < 4; ni++) { sc[ni][0] = sc[ni][1] = sc[ni][2] = sc[ni][3] = 0.f; }
#pragma unroll 2
        for (int ks = 0; ks < 8; ks++) {
            int k0 = ks * 16;
            uint32_t a[4], b[8];
            ldmx4(a, sb + SM_X + wm2 * RPITCH + k0 * 2 + aoffs);
            ldmx4t(b,     sb + SM_W + k0 * RPITCH + aoffs);
            ldmx4t(b + 4, sb + SM_W + k0 * RPITCH + 32 + aoffs);
#pragma unroll
            for (int ni = 0; ni < 4; ni++)
                mma16816(sc[ni], a, b + 2 * ni);
        }
#pragma unroll
        for (int ni = 0; ni < 4; ni++) {
            int n = ni * 8 + lc;
            *(float2*)(SC + (wm2 + l4) * 36 + n)     = make_float2(sc[ni][0], sc[ni][1]);
            *(float2*)(SC + (wm2 + l4 + 8) * 36 + n) = make_float2(sc[ni][2], sc[ni][3]);
        }
    }
    __syncthreads();

    // ---- softmax + recv: thread = (r 0..63, hd, half32) ----
    {
        const int r = tid & 63, hd = (tid >> 6) & 1, hf = tid >> 7;
        const int t = tb0 + r;
        float s[10];
#pragma unroll
        for (int j = 0; j < 10; j++) {
            float sv = (SC[r * 36 + hd * 16 + j] + C2S[hd * 16 + j]) * 0.125f;
            s[j] = fminf(fmaxf(sv, -CLAMPV), CLAMPV);
        }
        bool all = (t >= 10);
        float mx = -1e30f;
#pragma unroll
        for (int j = 0; j < 10; j++) {
            bool a = all || (j >= t - 5 && j <= t + 5);
            if (a) mx = fmaxf(mx, s[j]);
        }
        float p[10], den = 0.f;
#pragma unroll
        for (int j = 0; j < 10; j++) {
            bool a = all || (j >= t - 5 && j <= t + 5);
            p[j] = a ? expf(s[j] - mx) : 0.f;
            den += p[j];
        }
        float rinv = 1.f / den;
#pragma unroll
        for (int j = 0; j < 10; j++) p[j] *= rinv;
        const float* BF = BUFS + hd * 640 + hf * 32;
#pragma unroll
        for (int g = 0; g < 8; g++) {
            float4 acc = make_float4(0.f, 0.f, 0.f, 0.f);
#pragma unroll
            for (int j = 0; j < 10; j++) {
                float4 bv = *(const float4*)(BF + j * 64 + 4 * g);
                acc.x += p[j] * bv.x; acc.y += p[j] * bv.y;
                acc.z += p[j] * bv.z; acc.w += p[j] * bv.w;
            }
            *(ull*)(smem + SM_X + r * RPITCH + (hd * 64 + hf * 32 + 4 * g) * 2) = pack4h(acc);
        }
    }

    const int wm = (wid >> 2) * 32;
    const int wn = (wid & 3) * 32;

    float o[2][4][4];
#pragma unroll
    for (int ni = 0; ni < 4; ni++) {
        int col = wn + ni * 8 + lc;
        float bv0 = __ldg(&b2[col]), bv1 = __ldg(&b2[col + 1]);
#pragma unroll
        for (int mi = 0; mi < 2; mi++) {
            o[mi][ni][0] = bv0; o[mi][ni][1] = bv1;
            o[mi][ni][2] = bv0; o[mi][ni][3] = bv1;
        }
    }

    for (int ch = 0; ch < 4; ch++) {
        __syncthreads();
#pragma unroll
        for (int i = 0; i < 8; i++) {
            int idx = tid + i * 256;
            int k = idx >> 4, j = idx & 15;
            *(int4*)(smem + SM_W + k * RPITCH + j * 16) =
                *(const int4*)(w1h + k * 512 + ch * 128 + j * 8);
        }
        __syncthreads();

        float h[2][4][4];
#pragma unroll
        for (int ni = 0; ni < 4; ni++) {
            int col = wn + ni * 8 + lc;
            float bv0 = __ldg(&b1[ch * 128 + col]), bv1 = __ldg(&b1[ch * 128 + col + 1]);
#pragma unroll
            for (int mi = 0; mi < 2; mi++) {
                h[mi][ni][0] = bv0; h[mi][ni][1] = bv1;
                h[mi][ni][2] = bv0; h[mi][ni][3] = bv1;
            }
        }
#pragma unroll 2
        for (int ks = 0; ks < 8; ks++) {
            int k0 = ks * 16;
            uint32_t a[2][4], b[8];
#pragma unroll
            for (int mi = 0; mi < 2; mi++)
                ldmx4(a[mi], sb + SM_X + (wm + mi * 16) * RPITCH + k0 * 2 + aoffs);
            ldmx4t(b,     sb + SM_W + k0 * RPITCH + wn * 2 + aoffs);
            ldmx4t(b + 4, sb + SM_W + k0 * RPITCH + (wn + 16) * 2 + aoffs);
#pragma unroll
            for (int mi = 0; mi < 2; mi++)
#pragma unroll
                for (int ni = 0; ni < 4; ni++)
                    mma16816(h[mi][ni], a[mi], b + 2 * ni);
        }
#pragma unroll
        for (int mi = 0; mi < 2; mi++)
#pragma unroll
            for (int ni = 0; ni < 4; ni++) {
                int r_ = wm + mi * 16 + l4;
                int cb = (wn + ni * 8 + lc) * 2;
                unsigned short h0 = __half_as_ushort(__float2half_rn(gelu_fast(h[mi][ni][0])));
                unsigned short h1 = __half_as_ushort(__float2half_rn(gelu_fast(h[mi][ni][1])));
                unsigned short h2 = __half_as_ushort(__float2half_rn(gelu_fast(h[mi][ni][2])));
                unsigned short h3 = __half_as_ushort(__float2half_rn(gelu_fast(h[mi][ni][3])));
                *(uint32_t*)(smem + SM_H + r_ * RPITCH + cb) = (uint32_t)h0 | ((uint32_t)h1 << 16);
                *(uint32_t*)(smem + SM_H + (r_ + 8) * RPITCH + cb) = (uint32_t)h2 | ((uint32_t)h3 << 16);
            }
        __syncthreads();
#pragma unroll
        for (int i = 0; i < 8; i++) {
            int idx = tid + i * 256;
            int k = idx >> 4, j = idx & 15;
            *(int4*)(smem + SM_W + k * RPITCH + j * 16) =
                *(const int4*)(w2h + (ch * 128 + k) * 128 + j * 8);
        }
        __syncthreads();
#pragma unroll 2
        for (int ks = 0; ks < 8; ks++) {
            int k0 = ks * 16;
            uint32_t a[2][4], b[8];
#pragma unroll
            for (int mi = 0; mi < 2; mi++)
                ldmx4(a[mi], sb + SM_H + (wm + mi * 16) * RPITCH + k0 * 2 + aoffs);
            ldmx4t(b,     sb + SM_W + k0 * RPITCH + wn * 2 + aoffs);
            ldmx4t(b + 4, sb + SM_W + k0 * RPITCH + (wn + 16) * 2 + aoffs);
#pragma unroll
            for (int mi = 0; mi < 2; mi++)
#pragma unroll
                for (int ni = 0; ni < 4; ni++)
                    mma16816(o[mi][ni], a[mi], b + 2 * ni);
        }
    }

    // ---- epilogue: +xproj, LN(g2), LN(g3), scatter ----
    __syncthreads();
    float* OB = (float*)(smem);                // [64][132]
#pragma unroll
    for (int mi = 0; mi < 2; mi++)
#pragma unroll
        for (int ni = 0; ni < 4; ni++) {
            int r_ = wm + mi * 16 + l4;
            int c_ = wn + ni * 8 + lc;
            *(float2*)(OB + r_ * 132 + c_) = make_float2(o[mi][ni][0], o[mi][ni][1]);
            *(float2*)(OB + (r_ + 8) * 132 + c_) = make_float2(o[mi][ni][2], o[mi][ni][3]);
        }
    __syncthreads();

    const int m = tid & 63, cq = tid >> 6;
    const int c0 = cq * 32;
    float v[32];
    {
        const float* rp = xproj + (R0 + m) * 128 + c0;
#pragma unroll
        for (int g = 0; g < 8; g++) {
            float4 u = *(const float4*)(rp + 4 * g);
            float4 a = *(const float4*)(OB + m * 132 + c0 + 4 * g);
            v[4 * g + 0] = a.x + u.x; v[4 * g + 1] = a.y + u.y;
            v[4 * g + 2] = a.z + u.z; v[4 * g + 3] = a.w + u.w;
        }
    }
    {
        float s = 0.f, q = 0.f;
#pragma unroll
        for (int j = 0; j < 32; j++) { s += v[j]; q += v[j] * v[j]; }
        part[cq * 64 + m] = make_float2(s, q);
    }
    __syncthreads();
    {
        float s = 0.f, q = 0.f;
#pragma unroll
        for (int p_ = 0; p_ < 4; p_++) {
            float2 pp = part[p_ * 64 + m];
            s += pp.x; q += pp.y;
        }
        float mean = s * 0.0078125f;
        float rstd = rsqrtf(fmaxf(q * 0.0078125f - mean * mean, 0.f) + 1e-5f);
#pragma unroll
        for (int j = 0; j < 32; j++)
            v[j] = (v[j] - mean) * rstd * __ldg(&ga[c0 + j]) + __ldg(&ba[c0 + j]);
    }
    __syncthreads();
    {
        float s = 0.f, q = 0.f;
#pragma unroll
        for (int j = 0; j < 32; j++) { s += v[j]; q += v[j] * v[j]; }
        part[cq * 64 + m] = make_float2(s, q);
    }
    __syncthreads();
    float s = 0.f, q = 0.f;
#pragma unroll
    for (int p_ = 0; p_ < 4; p_++) {
        float2 pp = part[p_ * 64 + m];
        s += pp.x; q += pp.y;
    }
    float m2v = s * 0.0078125f;
    float rstd2 = rsqrtf(fmaxf(q * 0.0078125f - m2v * m2v, 0.f) + 1e-5f);
    int t = tb0 + m;
    int ob = (((bI << 10) + t) * 32 + lI) * 128 + c0;
#pragma unroll
    for (int g = 0; g < 8; g++) {
        float4 w;
        w.x = (v[4 * g + 0] - m2v) * rstd2 * __ldg(&gb[c0 + 4 * g + 0]) + __ldg(&bb[c0 + 4 * g + 0]);
        w.y = (v[4 * g + 1] - m2v) * rstd2 * __ldg(&gb[c0 + 4 * g + 1]) + __ldg(&bb[c0 + 4 * g + 1]);
        w.z = (v[4 * g + 2] - m2v) * rstd2 * __ldg(&gb[c0 + 4 * g + 2]) + __ldg(&bb[c0 + 4 * g + 2]);
        w.w = (v[4 * g + 3] - m2v) * rstd2 * __ldg(&gb[c0 + 4 * g + 3]) + __ldg(&bb[c0 + 4 * g + 3]);
        *(float4*)(out + ob + 4 * g) = w;
    }
}

// ============ merged K/V projection (blocks 0..127) + router proj (128..137) ============
#define SMEM_KV (34688 * 4)
__global__ __launch_bounds__(256, 1) void kvr_kernel(
    const float* __restrict__ xp,
    const float* __restrict__ wk, const float* __restrict__ bk,
    const float* __restrict__ wv, const float* __restrict__ bv,
    const float* __restrict__ router, const float* __restrict__ wr, const float* __restrict__ br,
    float* __restrict__ k15, float* __restrict__ v15, float* __restrict__ rp)
{
    extern __shared__ float sm[];
    const int tid = threadIdx.x;
    if (blockIdx.x < 128) {
        float* Xs = sm;
        float* Wks = sm + 1920;
        float* Wvs = sm + 18304;
        const int bl = blockIdx.x;
        for (int idx = tid; idx < 1920; idx += 256)
            Xs[idx] = xp[(bl * 1024 + (idx >> 7)) * 128 + (idx & 127)];
        for (int idx = tid; idx < 16384; idx += 256) { Wks[idx] = wk[idx]; Wvs[idx] = wv[idx]; }
        __syncthreads();
        const int m = tid >> 7, n = tid & 127;
        const float* W = m ? Wvs : Wks;
        const float bsv = m ? __ldg(&bv[n]) : __ldg(&bk[n]);
        float* o = m ? v15 : k15;
        for (int t = 0; t < 15; t++) {
            float acc = bsv;
#pragma unroll 8
            for (int k = 0; k < 128; k++) acc += Xs[t * 128 + k] * W[k * 128 + n];
            o[(bl * 15 + t) * 128 + n] = acc;
        }
    } else {
        float* Ws = sm;
        float* Rs = sm + 16384;
        const int row0 = (blockIdx.x - 128) * 32;
        for (int idx = tid; idx < 16384; idx += 256) Ws[idx] = wr[idx];
        for (int idx = tid; idx < 4096; idx += 256)
            Rs[idx] = router[(row0 + (idx >> 7)) * 128 + (idx & 127)];
        __syncthreads();
        const int n = tid & 127, rbase = (tid >> 7) * 16;
        const float bb_ = __ldg(&br[n]);
        for (int rr = 0; rr < 16; rr++) {
            int r = rbase + rr;
            float acc = bb_;
#pragma unroll 8
            for (int k = 0; k < 128; k++) acc += Rs[r * 128 + k] * Ws[k * 128 + n];
            rp[(row0 + r) * 128 + n] = acc;
        }
    }
}

// ============ buffer attention: warp per (bl, h, i) ============
__global__ __launch_bounds__(256) void buffer_warp(
    const float* __restrict__ rp, const float* __restrict__ k15,
    const float* __restrict__ v15, float* __restrict__ buf)
{
    const int w = (blockIdx.x << 3) + (threadIdx.x >> 5);
    const int lane = threadIdx.x & 31;
    const int bl = w / 20;
    const int rem = w - bl * 20;
    const int h = rem / 10, i = rem - (rem / 10) * 10;
    const int l = bl & 31;
    const float* q = rp + (l * 10 + i) * 128 + h * 64;
    const float q0 = q[lane], q1 = q[lane + 32];
    const int jlo = (i > 5) ? (i - 5) : 0;
    const int cnt = i + 5 - jlo + 1;
    float s[11];
#pragma unroll
    for (int jj = 0; jj < 11; jj++) {
        float d = 0.f;
        if (jj < cnt) {
            int base = (bl * 15 + jlo + jj) * 128 + h * 64;
            d = q0 * k15[base + lane] + q1 * k15[base + lane + 32];
        }
        d += __shfl_xor_sync(0xffffffffu, d, 16);
        d += __shfl_xor_sync(0xffffffffu, d, 8);
        d += __shfl_xor_sync(0xffffffffu, d, 4);
        d += __shfl_xor_sync(0xffffffffu, d, 2);
        d += __shfl_xor_sync(0xffffffffu, d, 1);
        s[jj] = fminf(fmaxf(d * 0.125f, -CLAMPV), CLAMPV);
    }
    float mx = -1e30f;
#pragma unroll
    for (int jj = 0; jj < 11; jj++) if (jj < cnt) mx = fmaxf(mx, s[jj]);
    float den = 0.f, o0 = 0.f, o1 = 0.f;
#pragma unroll
    for (int jj = 0; jj < 11; jj++) {
        if (jj < cnt) {
            float p = expf(s[jj] - mx);
            den += p;
            int vbase = (bl * 15 + jlo + jj) * 128 + h * 64;
            o0 += p * v15[vbase + lane];
            o1 += p * v15[vbase + lane + 32];
        }
    }
    float rinv = 1.f / den;
    int ob = ((bl * 2 + h) * 10 + i) * 64;
    buf[ob + lane] = o0 * rinv;
    buf[ob + lane + 32] = o1 * rinv;
}

// ============ M2 (parallel): 512 blocks = 4 per bl, 32 k-rows each ============
__global__ __launch_bounds__(256) void m2_fast(
    const float* __restrict__ wq, const float* __restrict__ bq,
    const float* __restrict__ bufp, __half* __restrict__ m2, float* __restrict__ c2)
{
    __shared__ float bufS[1280];
    const int bl = blockIdx.x >> 2;
    const int kbase = (blockIdx.x & 3) << 5;   // 0,32,64,96
    const int tid = threadIdx.x;
    for (int idx = tid; idx < 1280; idx += 256)
        bufS[idx] = bufp[bl * 1280 + idx];
    __syncthreads();
    const int n = tid & 31, h = n >> 4, j = n & 15;
    const int krel = tid >> 5;                  // 0..7
    const float* bv = bufS + h * 640 + j * 64;
#pragma unroll
    for (int it = 0; it < 4; it++) {
        int k = kbase + krel + (it << 3);
        float a0 = 0.f, a1 = 0.f;
        if (j < 10) {
            const float* wr = wq + k * 128 + h * 64;
#pragma unroll
            for (int dd = 0; dd < 32; dd++) {
                int d0 = (dd + n) & 63;
                int d1 = (dd + 32 + n) & 63;
                a0 += wr[d0] * bv[d0];
                a1 += wr[d1] * bv[d1];
            }
        }
        m2[(bl << 12) + (k << 5) + n] = __float2half_rn(a0 + a1);
    }
    if ((blockIdx.x & 3) == 0 && tid < 32) {
        float c = 0.f;
        if (j < 10) {
            const float* br_ = bq + h * 64;
#pragma unroll
            for (int dd = 0; dd < 64; dd++) {
                int d = (dd + n) & 63;
                c += br_[d] * bv[d];
            }
        }
        c2[(bl << 5) + tid] = c;
    }
}

// ============ launch ============
extern "C" void kernel_launch(void* const* d_in, const int* in_sizes, int n_in,
                              void* d_out, int out_size)
{
    const float* x        = (const float*)d_in[0];
    const float* router   = (const float*)d_in[1];
    const float* w_router = (const float*)d_in[2];
    const float* b_router = (const float*)d_in[3];
    const float* w_k      = (const float*)d_in[4];
    const float* b_k      = (const float*)d_in[5];
    const float* w_v      = (const float*)d_in[6];
    const float* b_v      = (const float*)d_in[7];
    const float* w_q      = (const float*)d_in[8];
    const float* b_q      = (const float*)d_in[9];
    const float* m1w1 = (const float*)d_in[10];
    const float* m1b1 = (const float*)d_in[11];
    const float* m1w2 = (const float*)d_in[12];
    const float* m1b2 = (const float*)d_in[13];
    const float* m2w1 = (const float*)d_in[14];
    const float* m2b1 = (const float*)d_in[15];
    const float* m2w2 = (const float*)d_in[16];
    const float* m2b2 = (const float*)d_in[17];
    const float* g1  = (const float*)d_in[18];
    const float* be1 = (const float*)d_in[19];
    const float* g2  = (const float*)d_in[20];
    const float* be2 = (const float*)d_in[21];
    const float* g3  = (const float*)d_in[22];
    const float* be3 = (const float*)d_in[23];
    float* out = (float*)d_out;

    float *xproj, *k15, *v15, *rproj, *bufp, *c2p;
    __half *w16, *m2p;
    cudaGetSymbolAddress((void**)&xproj, g_xproj);
    cudaGetSymbolAddress((void**)&k15,   g_k15);
    cudaGetSymbolAddress((void**)&v15,   g_v15);
    cudaGetSymbolAddress((void**)&rproj, g_rproj);
    cudaGetSymbolAddress((void**)&bufp,  g_buf);
    cudaGetSymbolAddress((void**)&w16,   g_w16);
    cudaGetSymbolAddress((void**)&m2p,   g_m2);
    cudaGetSymbolAddress((void**)&c2p,   g_c2);

    cudaFuncSetAttribute(fused_mlp1, cudaFuncAttributeMaxDynamicSharedMemorySize, SMEM_A);
    cudaFuncSetAttribute(fused_recv_mlp2, cudaFuncAttributeMaxDynamicSharedMemorySize, SMEM_B);
    cudaFuncSetAttribute(kvr_kernel, cudaFuncAttributeMaxDynamicSharedMemorySize, SMEM_KV);

    // 0. weights -> fp16
    cvt_weights<<<1024, 256>>>(m1w1, m1w2, m2w1, m2w2, w16);
    // 1. x_proj = LN(x + mlp1(x))   [64 rows/CTA, occ=2]
    fused_mlp1<<<2048, 256, SMEM_A>>>(
        x, w16, m1b1, w16 + 65536, m1b2, g1, be1, xproj);
    // 2. K/V (t<15) + router projection
    kvr_kernel<<<138, 256, SMEM_KV>>>(
        xproj, w_k, b_k, w_v, b_v, router, w_router, b_router, k15, v15, rproj);
    // 3. buffer attention (warp per (bl,h,i), measured 7.4us)
    buffer_warp<<<320, 256>>>(rproj, k15, v15, bufp);
    // 4. M2 = Wq @ buf (parallel, 4 blocks per bl), c2 = bq . buf
    m2_fast<<<512, 256>>>(w_q, b_q, bufp, m2p, c2p);
    // 5. scores + recv + mlp2 + LN2 + LN3 + scatter   [64 rows/CTA, occ=2]
    fused_recv_mlp2<<<2048, 256, SMEM_B>>>(
        bufp, xproj, m2p, c2p, w16 + 131072, m2b1, w16 + 196608, m2b2,
        g2, be2, g3, be3, out);
}